// round 3
// baseline (speedup 1.0000x reference)
#include <cuda_runtime.h>
#include <cstdint>

#define BATCH   4
#define SEQ     2048
#define EMBED   1024
#define HEADS   16
#define HDIM    64
#define NGLOBAL 4
#define WINDOW  256

#define MROWS   (BATCH * SEQ)          // 8192
#define QKV_N   (3 * EMBED)            // 3072

// Scratch (device globals: allocation-guard-safe)
__device__ float g_qkv[(size_t)MROWS * QKV_N];   // [8192, 3072]
__device__ float g_ctx[(size_t)MROWS * EMBED];   // [8192, 1024]

// ---------------------------------------------------------------------------
// SGEMM: C[M,N] = A[M,K] @ B[K,N] + bias[N]   (all row-major, fp32)
// 128x128 tile, BK=8, 256 threads, 8x8 per-thread register tile.
// M,N,K all multiples of tile sizes for our shapes -> no bounds checks.
// ---------------------------------------------------------------------------
__global__ __launch_bounds__(256) void sgemm128(
    int M, int N, int K,
    const float* __restrict__ A,
    const float* __restrict__ B,
    const float* __restrict__ bias,
    float* __restrict__ C)
{
    const int BK = 8;
    __shared__ float As[BK][128];   // A^T tile
    __shared__ float Bs[BK][128];

    const int tid = threadIdx.x;
    const int bm = blockIdx.y, bn = blockIdx.x;

    // A tile load: 128 rows x 8 k  = 1024 floats, float4 per thread
    const int arow = tid >> 1;
    const int acol = (tid & 1) << 2;
    // B tile load: 8 rows x 128 cols
    const int brow = tid >> 5;
    const int bcol = (tid & 31) << 2;

    const float* Ap = A + (size_t)(bm * 128 + arow) * K + acol;
    const float* Bp = B + (size_t)brow * N + bn * 128 + bcol;

    const int tr = (tid >> 4) << 3;   // 0..120
    const int tc = (tid & 15) << 3;   // 0..120

    float acc[8][8];
    #pragma unroll
    for (int i = 0; i < 8; i++)
        #pragma unroll
        for (int j = 0; j < 8; j++) acc[i][j] = 0.f;

    for (int kt = 0; kt < K; kt += BK) {
        float4 av = *(const float4*)Ap;
        float4 bv = *(const float4*)Bp;
        __syncthreads();
        As[acol + 0][arow] = av.x;
        As[acol + 1][arow] = av.y;
        As[acol + 2][arow] = av.z;
        As[acol + 3][arow] = av.w;
        *(float4*)&Bs[brow][bcol] = bv;
        __syncthreads();
        Ap += BK;
        Bp += (size_t)BK * N;

        #pragma unroll
        for (int k = 0; k < BK; k++) {
            float ra[8], rb[8];
            *(float4*)&ra[0] = *(const float4*)&As[k][tr];
            *(float4*)&ra[4] = *(const float4*)&As[k][tr + 4];
            *(float4*)&rb[0] = *(const float4*)&Bs[k][tc];
            *(float4*)&rb[4] = *(const float4*)&Bs[k][tc + 4];
            #pragma unroll
            for (int i = 0; i < 8; i++)
                #pragma unroll
                for (int j = 0; j < 8; j++)
                    acc[i][j] += ra[i] * rb[j];
        }
    }

    float bb[8];
    #pragma unroll
    for (int j = 0; j < 8; j++) bb[j] = bias[bn * 128 + tc + j];

    #pragma unroll
    for (int i = 0; i < 8; i++) {
        const int row = bm * 128 + tr + i;
        float* Crow = C + (size_t)row * N + bn * 128 + tc;
        float4 o0, o1;
        o0.x = acc[i][0] + bb[0]; o0.y = acc[i][1] + bb[1];
        o0.z = acc[i][2] + bb[2]; o0.w = acc[i][3] + bb[3];
        o1.x = acc[i][4] + bb[4]; o1.y = acc[i][5] + bb[5];
        o1.z = acc[i][6] + bb[6]; o1.w = acc[i][7] + bb[7];
        *(float4*)(Crow)     = o0;
        *(float4*)(Crow + 4) = o1;
    }
}

// ---------------------------------------------------------------------------
// Attention: one CTA = (b, h, 64-query block). Flash-style online softmax.
// 256 threads as 16x16 grid; each thread owns a 4x4 score tile and a 4(row)x4(dim)
// output tile. Row stats reduced via shfl across the 16-lane tx group.
// ---------------------------------------------------------------------------
#define SMPAD 65
#define ATTN_SMEM (4 * 64 * SMPAD * 4)

__global__ __launch_bounds__(256) void attn_kernel(
    const float* __restrict__ qkv,
    float* __restrict__ ctx)
{
    extern __shared__ float sm[];
    float* Qs = sm;
    float* Ks = sm + 64 * SMPAD;
    float* Vs = sm + 2 * 64 * SMPAD;
    float* Ps = sm + 3 * 64 * SMPAD;

    const int qb = blockIdx.x;
    const int h  = blockIdx.y;
    const int b  = blockIdx.z;
    const int qs = qb << 6;
    const bool isg = (h < NGLOBAL);

    const int tid = threadIdx.x;
    const int tx = tid & 15, ty = tid >> 4;
    const int r0 = ty << 2, c0 = tx << 2;

    const float NEG_INF = __int_as_float(0xff800000u);

    // Load Q tile (scaled by HDIM^-0.5 = 0.125)
    const float* Qg = qkv + ((size_t)(b * SEQ + qs)) * QKV_N + h * HDIM;
    #pragma unroll
    for (int it = 0; it < 4; it++) {
        int i = tid + it * 256;
        int r = i >> 4, d4 = (i & 15) << 2;
        float4 v = *(const float4*)(Qg + (size_t)r * QKV_N + d4);
        Qs[r * SMPAD + d4 + 0] = v.x * 0.125f;
        Qs[r * SMPAD + d4 + 1] = v.y * 0.125f;
        Qs[r * SMPAD + d4 + 2] = v.z * 0.125f;
        Qs[r * SMPAD + d4 + 3] = v.w * 0.125f;
    }

    float m[4], l[4], o[4][4];
    #pragma unroll
    for (int i = 0; i < 4; i++) {
        m[i] = -1e30f;
        l[i] = 0.f;
        #pragma unroll
        for (int j = 0; j < 4; j++) o[i][j] = 0.f;
    }

    const int kb0 = isg ? 0 : max(0, qb - 4);
    for (int kb = kb0; kb <= qb; kb++) {
        const int ks = kb << 6;
        const float* Kg = qkv + ((size_t)(b * SEQ + ks)) * QKV_N + EMBED + h * HDIM;
        const float* Vg = Kg + EMBED;

        __syncthreads();   // prior iteration's reads of Ks/Vs complete; Q writes ordered
        #pragma unroll
        for (int it = 0; it < 4; it++) {
            int i = tid + it * 256;
            int r = i >> 4, d4 = (i & 15) << 2;
            float4 kv = *(const float4*)(Kg + (size_t)r * QKV_N + d4);
            float4 vv = *(const float4*)(Vg + (size_t)r * QKV_N + d4);
            Ks[r * SMPAD + d4 + 0] = kv.x;
            Ks[r * SMPAD + d4 + 1] = kv.y;
            Ks[r * SMPAD + d4 + 2] = kv.z;
            Ks[r * SMPAD + d4 + 3] = kv.w;
            Vs[r * SMPAD + d4 + 0] = vv.x;
            Vs[r * SMPAD + d4 + 1] = vv.y;
            Vs[r * SMPAD + d4 + 2] = vv.z;
            Vs[r * SMPAD + d4 + 3] = vv.w;
        }
        __syncthreads();

        // S = Q @ K^T (4x4 per thread)
        float s[4][4];
        #pragma unroll
        for (int i = 0; i < 4; i++)
            #pragma unroll
            for (int j = 0; j < 4; j++) s[i][j] = 0.f;

        #pragma unroll 8
        for (int d = 0; d < 64; d++) {
            float qv[4], kv[4];
            #pragma unroll
            for (int i = 0; i < 4; i++) qv[i] = Qs[(r0 + i) * SMPAD + d];
            #pragma unroll
            for (int j = 0; j < 4; j++) kv[j] = Ks[(c0 + j) * SMPAD + d];
            #pragma unroll
            for (int i = 0; i < 4; i++)
                #pragma unroll
                for (int j = 0; j < 4; j++)
                    s[i][j] += qv[i] * kv[j];
        }

        // Mask
        #pragma unroll
        for (int i = 0; i < 4; i++) {
            const int gi = qs + r0 + i;
            #pragma unroll
            for (int j = 0; j < 4; j++) {
                const int gj = ks + c0 + j;
                bool ok = (gj <= gi) && (isg || (gi - gj) <= WINDOW);
                if (!ok) s[i][j] = NEG_INF;
            }
        }

        // Online softmax update
        #pragma unroll
        for (int i = 0; i < 4; i++) {
            float mx = fmaxf(fmaxf(s[i][0], s[i][1]), fmaxf(s[i][2], s[i][3]));
            #pragma unroll
            for (int off = 8; off > 0; off >>= 1)
                mx = fmaxf(mx, __shfl_xor_sync(0xffffffffu, mx, off));
            const float mn = fmaxf(m[i], mx);
            float sum = 0.f;
            #pragma unroll
            for (int j = 0; j < 4; j++) {
                float p = __expf(s[i][j] - mn);
                s[i][j] = p;
                sum += p;
            }
            #pragma unroll
            for (int off = 8; off > 0; off >>= 1)
                sum += __shfl_xor_sync(0xffffffffu, sum, off);
            const float alpha = __expf(m[i] - mn);
            l[i] = l[i] * alpha + sum;
            m[i] = mn;
            #pragma unroll
            for (int j = 0; j < 4; j++) o[i][j] *= alpha;
        }

        // P to smem
        #pragma unroll
        for (int i = 0; i < 4; i++)
            #pragma unroll
            for (int j = 0; j < 4; j++)
                Ps[(r0 + i) * SMPAD + c0 + j] = s[i][j];
        __syncthreads();

        // O += P @ V
        #pragma unroll 8
        for (int c = 0; c < 64; c++) {
            float pv[4], vv[4];
            #pragma unroll
            for (int i = 0; i < 4; i++) pv[i] = Ps[(r0 + i) * SMPAD + c];
            #pragma unroll
            for (int j = 0; j < 4; j++) vv[j] = Vs[c * SMPAD + c0 + j];
            #pragma unroll
            for (int i = 0; i < 4; i++)
                #pragma unroll
                for (int j = 0; j < 4; j++)
                    o[i][j] += pv[i] * vv[j];
        }
    }

    // Epilogue: normalize + write ctx[b, s, h*64 + d]
    #pragma unroll
    for (int i = 0; i < 4; i++) {
        const float inv = 1.f / l[i];
        const int row = b * SEQ + qs + r0 + i;
        float4 out;
        out.x = o[i][0] * inv;
        out.y = o[i][1] * inv;
        out.z = o[i][2] * inv;
        out.w = o[i][3] * inv;
        *(float4*)(ctx + (size_t)row * EMBED + h * HDIM + c0) = out;
    }
}

// ---------------------------------------------------------------------------
// Launch
// ---------------------------------------------------------------------------
extern "C" void kernel_launch(void* const* d_in, const int* in_sizes, int n_in,
                              void* d_out, int out_size)
{
    const float* x     = (const float*)d_in[0];
    const float* w_qkv = (const float*)d_in[1];
    const float* b_qkv = (const float*)d_in[2];
    const float* w_out = (const float*)d_in[3];
    const float* b_out = (const float*)d_in[4];
    float* out = (float*)d_out;

    float* qkv_ptr = nullptr;
    float* ctx_ptr = nullptr;
    cudaGetSymbolAddress((void**)&qkv_ptr, g_qkv);
    cudaGetSymbolAddress((void**)&ctx_ptr, g_ctx);

    // Opt-in >48KB dynamic smem for the attention kernel (idempotent; legal
    // during graph capture since it is not a stream-ordered operation).
    cudaFuncSetAttribute(attn_kernel, cudaFuncAttributeMaxDynamicSharedMemorySize,
                         ATTN_SMEM);

    // 1) QKV projection: [8192,1024] @ [1024,3072] + b
    {
        dim3 grid(QKV_N / 128, MROWS / 128);
        sgemm128<<<grid, 256>>>(MROWS, QKV_N, EMBED, x, w_qkv, b_qkv, qkv_ptr);
    }
    // 2) Attention
    {
        dim3 grid(SEQ / 64, HEADS, BATCH);
        attn_kernel<<<grid, 256, ATTN_SMEM>>>(qkv_ptr, ctx_ptr);
    }
    // 3) Output projection: [8192,1024] @ [1024,1024] + b
    {
        dim3 grid(EMBED / 128, MROWS / 128);
        sgemm128<<<grid, 256>>>(MROWS, EMBED, EMBED, ctx_ptr, w_out, b_out, out);
    }
}

// round 4
// speedup vs baseline: 1.6797x; 1.6797x over previous
#include <cuda_runtime.h>
#include <cuda_bf16.h>
#include <cstdint>

#define BATCH   4
#define SEQ     2048
#define EMBED   1024
#define HEADS   16
#define HDIM    64
#define NGLOBAL 4
#define WINDOW  256

#define MROWS   (BATCH * SEQ)          // 8192
#define QKV_N   (3 * EMBED)            // 3072

// ---------------------------------------------------------------------------
// Scratch (device globals: allocation-guard-safe)
// ---------------------------------------------------------------------------
__device__ float        g_qkv [(size_t)MROWS * QKV_N];    // fp32 QKV
__device__ __nv_bfloat16 g_xh  [(size_t)MROWS * EMBED];
__device__ __nv_bfloat16 g_xl  [(size_t)MROWS * EMBED];
__device__ __nv_bfloat16 g_wqh [(size_t)EMBED * QKV_N];
__device__ __nv_bfloat16 g_wql [(size_t)EMBED * QKV_N];
__device__ __nv_bfloat16 g_woh [(size_t)EMBED * EMBED];
__device__ __nv_bfloat16 g_wol [(size_t)EMBED * EMBED];
__device__ __nv_bfloat16 g_ctxh[(size_t)MROWS * EMBED];
__device__ __nv_bfloat16 g_ctxl[(size_t)MROWS * EMBED];

// ---------------------------------------------------------------------------
// fp32 -> (bf16 hi, bf16 lo) split, vectorized
// ---------------------------------------------------------------------------
__global__ void split_kernel(const float* __restrict__ src,
                             __nv_bfloat16* __restrict__ hi,
                             __nv_bfloat16* __restrict__ lo, int n4)
{
    int i = blockIdx.x * blockDim.x + threadIdx.x;
    if (i >= n4) return;
    float4 v = ((const float4*)src)[i];
    __nv_bfloat16 h0 = __float2bfloat16(v.x);
    __nv_bfloat16 h1 = __float2bfloat16(v.y);
    __nv_bfloat16 h2 = __float2bfloat16(v.z);
    __nv_bfloat16 h3 = __float2bfloat16(v.w);
    __nv_bfloat16 l0 = __float2bfloat16(v.x - __bfloat162float(h0));
    __nv_bfloat16 l1 = __float2bfloat16(v.y - __bfloat162float(h1));
    __nv_bfloat16 l2 = __float2bfloat16(v.z - __bfloat162float(h2));
    __nv_bfloat16 l3 = __float2bfloat16(v.w - __bfloat162float(h3));
    ushort4 hv, lv;
    hv.x = __bfloat16_as_ushort(h0); hv.y = __bfloat16_as_ushort(h1);
    hv.z = __bfloat16_as_ushort(h2); hv.w = __bfloat16_as_ushort(h3);
    lv.x = __bfloat16_as_ushort(l0); lv.y = __bfloat16_as_ushort(l1);
    lv.z = __bfloat16_as_ushort(l2); lv.w = __bfloat16_as_ushort(l3);
    ((ushort4*)hi)[i] = hv;
    ((ushort4*)lo)[i] = lv;
}

// ---------------------------------------------------------------------------
// Tensor-core GEMM with bf16-split fp32 emulation.
// C[M,N] = (Ah+Al)(Bh+Bl) + bias  ~=  Ah*Bh + Ah*Bl + Al*Bh  (fp32 accum)
// 128x128x32 CTA tile, 8 warps (2x4), 64x32 warp tile, mma.m16n8k16,
// cp.async 2-stage pipeline, conflict-free padded smem.
// ---------------------------------------------------------------------------
#define BM 128
#define BN 128
#define BKK 32
#define ALD (BKK + 8)          // 40 halves  (80B row: ldmatrix conflict-free)
#define BLD (BN + 8)           // 136 halves (272B row: conflict-free)
#define OFF_AH 0
#define OFF_AL (BM * ALD)                  // 5120
#define OFF_BH (2 * BM * ALD)              // 10240
#define OFF_BL (2 * BM * ALD + BKK * BLD)  // 14592
#define STAGE_H (2 * BM * ALD + 2 * BKK * BLD)   // 18944 halves
#define GEMM_SMEM (2 * STAGE_H * 2)              // 75776 bytes

__device__ __forceinline__ void cp16(uint32_t dst, const void* src) {
    asm volatile("cp.async.cg.shared.global [%0], [%1], 16;\n"
                 :: "r"(dst), "l"(src));
}
__device__ __forceinline__ void ldsm4(uint32_t& r0, uint32_t& r1,
                                      uint32_t& r2, uint32_t& r3, uint32_t a) {
    asm volatile("ldmatrix.sync.aligned.m8n8.x4.shared.b16 {%0,%1,%2,%3},[%4];\n"
                 : "=r"(r0), "=r"(r1), "=r"(r2), "=r"(r3) : "r"(a));
}
__device__ __forceinline__ void ldsm4t(uint32_t& r0, uint32_t& r1,
                                       uint32_t& r2, uint32_t& r3, uint32_t a) {
    asm volatile("ldmatrix.sync.aligned.m8n8.x4.trans.shared.b16 {%0,%1,%2,%3},[%4];\n"
                 : "=r"(r0), "=r"(r1), "=r"(r2), "=r"(r3) : "r"(a));
}
__device__ __forceinline__ void mma16816(float* c, const uint32_t* a,
                                         const uint32_t* b) {
    asm volatile(
        "mma.sync.aligned.m16n8k16.row.col.f32.bf16.bf16.f32 "
        "{%0,%1,%2,%3},{%4,%5,%6,%7},{%8,%9},{%0,%1,%2,%3};\n"
        : "+f"(c[0]), "+f"(c[1]), "+f"(c[2]), "+f"(c[3])
        : "r"(a[0]), "r"(a[1]), "r"(a[2]), "r"(a[3]), "r"(b[0]), "r"(b[1]));
}

__global__ __launch_bounds__(256, 1) void bsgemm(
    int M, int N, int K,
    const __nv_bfloat16* __restrict__ Ah, const __nv_bfloat16* __restrict__ Al,
    const __nv_bfloat16* __restrict__ Bh, const __nv_bfloat16* __restrict__ Bl,
    const float* __restrict__ bias, float* __restrict__ C)
{
    extern __shared__ __nv_bfloat16 sm[];
    const int tid = threadIdx.x;
    const int bm = blockIdx.y, bn = blockIdx.x;
    const int wid = tid >> 5, lane = tid & 31;
    const int wm = (wid >> 2) * 64, wn = (wid & 3) * 32;

    const uint32_t smem_base = (uint32_t)__cvta_generic_to_shared(sm);

    float acc[4][4][4];
    #pragma unroll
    for (int mi = 0; mi < 4; mi++)
        #pragma unroll
        for (int nj = 0; nj < 4; nj++)
            #pragma unroll
            for (int r = 0; r < 4; r++) acc[mi][nj][r] = 0.f;

    const int NK = K / BKK;

    // -------- stage loader (8 cp.async per thread) --------
    auto load_stage = [&](int s, int kt) {
        const uint32_t base = smem_base + s * (STAGE_H * 2);
        const int k0 = kt * BKK;
        #pragma unroll
        for (int i = 0; i < 2; i++) {
            int idx = tid + i * 256;             // 0..511
            int r  = idx >> 2, c  = (idx & 3) << 3;   // A: 128 rows x 4 chunks
            size_t aoff = (size_t)(bm * BM + r) * K + k0 + c;
            cp16(base + (OFF_AH + r * ALD + c) * 2, Ah + aoff);
            cp16(base + (OFF_AL + r * ALD + c) * 2, Al + aoff);
            int rb = idx >> 4, cb = (idx & 15) << 3;  // B: 32 rows x 16 chunks
            size_t boff = (size_t)(k0 + rb) * N + bn * BN + cb;
            cp16(base + (OFF_BH + rb * BLD + cb) * 2, Bh + boff);
            cp16(base + (OFF_BL + rb * BLD + cb) * 2, Bl + boff);
        }
        asm volatile("cp.async.commit_group;\n");
    };

    load_stage(0, 0);

    for (int kt = 0; kt < NK; kt++) {
        if (kt + 1 < NK) {
            load_stage((kt + 1) & 1, kt + 1);
            asm volatile("cp.async.wait_group 1;\n");
        } else {
            asm volatile("cp.async.wait_group 0;\n");
        }
        __syncthreads();

        const uint32_t base = smem_base + (kt & 1) * (STAGE_H * 2);

        #pragma unroll
        for (int ks = 0; ks < 2; ks++) {
            const int k = ks * 16;
            uint32_t ah[4][4], al[4][4];
            #pragma unroll
            for (int mi = 0; mi < 4; mi++) {
                int row = wm + mi * 16 + (lane & 15);
                int col = k + (lane >> 4) * 8;
                ldsm4(ah[mi][0], ah[mi][1], ah[mi][2], ah[mi][3],
                      base + (OFF_AH + row * ALD + col) * 2);
                ldsm4(al[mi][0], al[mi][1], al[mi][2], al[mi][3],
                      base + (OFF_AL + row * ALD + col) * 2);
            }
            uint32_t bh[2][4], bl[2][4];
            #pragma unroll
            for (int ng = 0; ng < 2; ng++) {
                int row = k + (lane & 15);
                int col = wn + ng * 16 + (lane >> 4) * 8;
                ldsm4t(bh[ng][0], bh[ng][1], bh[ng][2], bh[ng][3],
                       base + (OFF_BH + row * BLD + col) * 2);
                ldsm4t(bl[ng][0], bl[ng][1], bl[ng][2], bl[ng][3],
                       base + (OFF_BL + row * BLD + col) * 2);
            }
            #pragma unroll
            for (int mi = 0; mi < 4; mi++) {
                #pragma unroll
                for (int nj = 0; nj < 4; nj++) {
                    const uint32_t* bhp = &bh[nj >> 1][(nj & 1) * 2];
                    const uint32_t* blp = &bl[nj >> 1][(nj & 1) * 2];
                    mma16816(acc[mi][nj], ah[mi], bhp);
                    mma16816(acc[mi][nj], ah[mi], blp);
                    mma16816(acc[mi][nj], al[mi], bhp);
                }
            }
        }
        __syncthreads();
    }

    // -------- epilogue: + bias, fp32 store --------
    #pragma unroll
    for (int mi = 0; mi < 4; mi++) {
        #pragma unroll
        for (int nj = 0; nj < 4; nj++) {
            int r0 = bm * BM + wm + mi * 16 + (lane >> 2);
            int c0 = bn * BN + wn + nj * 8 + (lane & 3) * 2;
            float b0 = bias[c0], b1 = bias[c0 + 1];
            float2 v0 = make_float2(acc[mi][nj][0] + b0, acc[mi][nj][1] + b1);
            float2 v1 = make_float2(acc[mi][nj][2] + b0, acc[mi][nj][3] + b1);
            *(float2*)&C[(size_t)r0 * N + c0]        = v0;
            *(float2*)&C[(size_t)(r0 + 8) * N + c0]  = v1;
        }
    }
}

// ---------------------------------------------------------------------------
// Attention: one CTA = (b, h, 64-query block). Flash-style online softmax.
// Unchanged from baseline except the epilogue writes ctx as bf16 hi/lo split.
// ---------------------------------------------------------------------------
#define SMPAD 65
#define ATTN_SMEM (4 * 64 * SMPAD * 4)

__global__ __launch_bounds__(256) void attn_kernel(
    const float* __restrict__ qkv,
    __nv_bfloat16* __restrict__ ctxh,
    __nv_bfloat16* __restrict__ ctxl)
{
    extern __shared__ float smf[];
    float* Qs = smf;
    float* Ks = smf + 64 * SMPAD;
    float* Vs = smf + 2 * 64 * SMPAD;
    float* Ps = smf + 3 * 64 * SMPAD;

    const int qb = blockIdx.x;
    const int h  = blockIdx.y;
    const int b  = blockIdx.z;
    const int qs = qb << 6;
    const bool isg = (h < NGLOBAL);

    const int tid = threadIdx.x;
    const int tx = tid & 15, ty = tid >> 4;
    const int r0 = ty << 2, c0 = tx << 2;

    const float NEG_INF = __int_as_float(0xff800000u);

    const float* Qg = qkv + ((size_t)(b * SEQ + qs)) * QKV_N + h * HDIM;
    #pragma unroll
    for (int it = 0; it < 4; it++) {
        int i = tid + it * 256;
        int r = i >> 4, d4 = (i & 15) << 2;
        float4 v = *(const float4*)(Qg + (size_t)r * QKV_N + d4);
        Qs[r * SMPAD + d4 + 0] = v.x * 0.125f;
        Qs[r * SMPAD + d4 + 1] = v.y * 0.125f;
        Qs[r * SMPAD + d4 + 2] = v.z * 0.125f;
        Qs[r * SMPAD + d4 + 3] = v.w * 0.125f;
    }

    float m[4], l[4], o[4][4];
    #pragma unroll
    for (int i = 0; i < 4; i++) {
        m[i] = -1e30f; l[i] = 0.f;
        #pragma unroll
        for (int j = 0; j < 4; j++) o[i][j] = 0.f;
    }

    const int kb0 = isg ? 0 : max(0, qb - 4);
    for (int kb = kb0; kb <= qb; kb++) {
        const int ks = kb << 6;
        const float* Kg = qkv + ((size_t)(b * SEQ + ks)) * QKV_N + EMBED + h * HDIM;
        const float* Vg = Kg + EMBED;

        __syncthreads();
        #pragma unroll
        for (int it = 0; it < 4; it++) {
            int i = tid + it * 256;
            int r = i >> 4, d4 = (i & 15) << 2;
            float4 kv = *(const float4*)(Kg + (size_t)r * QKV_N + d4);
            float4 vv = *(const float4*)(Vg + (size_t)r * QKV_N + d4);
            Ks[r * SMPAD + d4 + 0] = kv.x;
            Ks[r * SMPAD + d4 + 1] = kv.y;
            Ks[r * SMPAD + d4 + 2] = kv.z;
            Ks[r * SMPAD + d4 + 3] = kv.w;
            Vs[r * SMPAD + d4 + 0] = vv.x;
            Vs[r * SMPAD + d4 + 1] = vv.y;
            Vs[r * SMPAD + d4 + 2] = vv.z;
            Vs[r * SMPAD + d4 + 3] = vv.w;
        }
        __syncthreads();

        float s[4][4];
        #pragma unroll
        for (int i = 0; i < 4; i++)
            #pragma unroll
            for (int j = 0; j < 4; j++) s[i][j] = 0.f;

        #pragma unroll 8
        for (int d = 0; d < 64; d++) {
            float qv[4], kv[4];
            #pragma unroll
            for (int i = 0; i < 4; i++) qv[i] = Qs[(r0 + i) * SMPAD + d];
            #pragma unroll
            for (int j = 0; j < 4; j++) kv[j] = Ks[(c0 + j) * SMPAD + d];
            #pragma unroll
            for (int i = 0; i < 4; i++)
                #pragma unroll
                for (int j = 0; j < 4; j++)
                    s[i][j] += qv[i] * kv[j];
        }

        #pragma unroll
        for (int i = 0; i < 4; i++) {
            const int gi = qs + r0 + i;
            #pragma unroll
            for (int j = 0; j < 4; j++) {
                const int gj = ks + c0 + j;
                bool ok = (gj <= gi) && (isg || (gi - gj) <= WINDOW);
                if (!ok) s[i][j] = NEG_INF;
            }
        }

        #pragma unroll
        for (int i = 0; i < 4; i++) {
            float mx = fmaxf(fmaxf(s[i][0], s[i][1]), fmaxf(s[i][2], s[i][3]));
            #pragma unroll
            for (int off = 8; off > 0; off >>= 1)
                mx = fmaxf(mx, __shfl_xor_sync(0xffffffffu, mx, off));
            const float mn = fmaxf(m[i], mx);
            float sum = 0.f;
            #pragma unroll
            for (int j = 0; j < 4; j++) {
                float p = __expf(s[i][j] - mn);
                s[i][j] = p;
                sum += p;
            }
            #pragma unroll
            for (int off = 8; off > 0; off >>= 1)
                sum += __shfl_xor_sync(0xffffffffu, sum, off);
            const float alpha = __expf(m[i] - mn);
            l[i] = l[i] * alpha + sum;
            m[i] = mn;
            #pragma unroll
            for (int j = 0; j < 4; j++) o[i][j] *= alpha;
        }

        #pragma unroll
        for (int i = 0; i < 4; i++)
            #pragma unroll
            for (int j = 0; j < 4; j++)
                Ps[(r0 + i) * SMPAD + c0 + j] = s[i][j];
        __syncthreads();

        #pragma unroll 8
        for (int c = 0; c < 64; c++) {
            float pv[4], vv[4];
            #pragma unroll
            for (int i = 0; i < 4; i++) pv[i] = Ps[(r0 + i) * SMPAD + c];
            #pragma unroll
            for (int j = 0; j < 4; j++) vv[j] = Vs[c * SMPAD + c0 + j];
            #pragma unroll
            for (int i = 0; i < 4; i++)
                #pragma unroll
                for (int j = 0; j < 4; j++)
                    o[i][j] += pv[i] * vv[j];
        }
    }

    // Epilogue: normalize + write ctx split into bf16 hi/lo
    #pragma unroll
    for (int i = 0; i < 4; i++) {
        const float inv = 1.f / l[i];
        const int row = b * SEQ + qs + r0 + i;
        const size_t off = (size_t)row * EMBED + h * HDIM + c0;
        ushort4 hv, lv;
        float vals[4];
        #pragma unroll
        for (int j = 0; j < 4; j++) vals[j] = o[i][j] * inv;
        __nv_bfloat16 h0 = __float2bfloat16(vals[0]);
        __nv_bfloat16 h1 = __float2bfloat16(vals[1]);
        __nv_bfloat16 h2 = __float2bfloat16(vals[2]);
        __nv_bfloat16 h3 = __float2bfloat16(vals[3]);
        hv.x = __bfloat16_as_ushort(h0); hv.y = __bfloat16_as_ushort(h1);
        hv.z = __bfloat16_as_ushort(h2); hv.w = __bfloat16_as_ushort(h3);
        lv.x = __bfloat16_as_ushort(__float2bfloat16(vals[0] - __bfloat162float(h0)));
        lv.y = __bfloat16_as_ushort(__float2bfloat16(vals[1] - __bfloat162float(h1)));
        lv.z = __bfloat16_as_ushort(__float2bfloat16(vals[2] - __bfloat162float(h2)));
        lv.w = __bfloat16_as_ushort(__float2bfloat16(vals[3] - __bfloat162float(h3)));
        *(ushort4*)(ctxh + off) = hv;
        *(ushort4*)(ctxl + off) = lv;
    }
}

// ---------------------------------------------------------------------------
// Launch
// ---------------------------------------------------------------------------
extern "C" void kernel_launch(void* const* d_in, const int* in_sizes, int n_in,
                              void* d_out, int out_size)
{
    const float* x     = (const float*)d_in[0];
    const float* w_qkv = (const float*)d_in[1];
    const float* b_qkv = (const float*)d_in[2];
    const float* w_out = (const float*)d_in[3];
    const float* b_out = (const float*)d_in[4];
    float* out = (float*)d_out;

    float *qkv_ptr;
    __nv_bfloat16 *xh, *xl, *wqh, *wql, *woh, *wol, *ctxh, *ctxl;
    cudaGetSymbolAddress((void**)&qkv_ptr, g_qkv);
    cudaGetSymbolAddress((void**)&xh,  g_xh);
    cudaGetSymbolAddress((void**)&xl,  g_xl);
    cudaGetSymbolAddress((void**)&wqh, g_wqh);
    cudaGetSymbolAddress((void**)&wql, g_wql);
    cudaGetSymbolAddress((void**)&woh, g_woh);
    cudaGetSymbolAddress((void**)&wol, g_wol);
    cudaGetSymbolAddress((void**)&ctxh, g_ctxh);
    cudaGetSymbolAddress((void**)&ctxl, g_ctxl);

    cudaFuncSetAttribute(attn_kernel, cudaFuncAttributeMaxDynamicSharedMemorySize,
                         ATTN_SMEM);
    cudaFuncSetAttribute(bsgemm, cudaFuncAttributeMaxDynamicSharedMemorySize,
                         GEMM_SMEM);

    // 0) Splits: x, w_qkv, w_out  -> bf16 hi/lo
    {
        int n4;
        n4 = MROWS * EMBED / 4;
        split_kernel<<<(n4 + 255) / 256, 256>>>(x, xh, xl, n4);
        n4 = EMBED * QKV_N / 4;
        split_kernel<<<(n4 + 255) / 256, 256>>>(w_qkv, wqh, wql, n4);
        n4 = EMBED * EMBED / 4;
        split_kernel<<<(n4 + 255) / 256, 256>>>(w_out, woh, wol, n4);
    }

    // 1) QKV projection (tensor cores): [8192,1024] @ [1024,3072] + b
    {
        dim3 grid(QKV_N / BN, MROWS / BM);
        bsgemm<<<grid, 256, GEMM_SMEM>>>(MROWS, QKV_N, EMBED,
                                         xh, xl, wqh, wql, b_qkv, qkv_ptr);
    }
    // 2) Attention (fp32 SIMT), writes ctx as bf16 hi/lo
    {
        dim3 grid(SEQ / 64, HEADS, BATCH);
        attn_kernel<<<grid, 256, ATTN_SMEM>>>(qkv_ptr, ctxh, ctxl);
    }
    // 3) Output projection (tensor cores): [8192,1024] @ [1024,1024] + b
    {
        dim3 grid(EMBED / BN, MROWS / BM);
        bsgemm<<<grid, 256, GEMM_SMEM>>>(MROWS, EMBED, EMBED,
                                         ctxh, ctxl, woh, wol, b_out, out);
    }
}

// round 5
// speedup vs baseline: 2.4279x; 1.4454x over previous
#include <cuda_runtime.h>
#include <cuda_bf16.h>
#include <cstdint>

#define BATCH   4
#define SEQ     2048
#define EMBED   1024
#define HEADS   16
#define HDIM    64
#define NGLOBAL 4
#define WINDOW  256

#define MROWS   (BATCH * SEQ)          // 8192
#define QKV_N   (3 * EMBED)            // 3072

// ---------------------------------------------------------------------------
// Scratch (device globals: allocation-guard-safe)
// ---------------------------------------------------------------------------
__device__ __nv_bfloat16 g_qkvh[(size_t)MROWS * QKV_N];
__device__ __nv_bfloat16 g_qkvl[(size_t)MROWS * QKV_N];
__device__ __nv_bfloat16 g_xh  [(size_t)MROWS * EMBED];
__device__ __nv_bfloat16 g_xl  [(size_t)MROWS * EMBED];
__device__ __nv_bfloat16 g_wqh [(size_t)EMBED * QKV_N];
__device__ __nv_bfloat16 g_wql [(size_t)EMBED * QKV_N];
__device__ __nv_bfloat16 g_woh [(size_t)EMBED * EMBED];
__device__ __nv_bfloat16 g_wol [(size_t)EMBED * EMBED];
__device__ __nv_bfloat16 g_ctxh[(size_t)MROWS * EMBED];
__device__ __nv_bfloat16 g_ctxl[(size_t)MROWS * EMBED];

// ---------------------------------------------------------------------------
// Helpers
// ---------------------------------------------------------------------------
__device__ __forceinline__ void cp16(uint32_t dst, const void* src) {
    asm volatile("cp.async.cg.shared.global [%0], [%1], 16;\n"
                 :: "r"(dst), "l"(src));
}
__device__ __forceinline__ void ldsm4(uint32_t& r0, uint32_t& r1,
                                      uint32_t& r2, uint32_t& r3, uint32_t a) {
    asm volatile("ldmatrix.sync.aligned.m8n8.x4.shared.b16 {%0,%1,%2,%3},[%4];\n"
                 : "=r"(r0), "=r"(r1), "=r"(r2), "=r"(r3) : "r"(a));
}
__device__ __forceinline__ void ldsm4t(uint32_t& r0, uint32_t& r1,
                                       uint32_t& r2, uint32_t& r3, uint32_t a) {
    asm volatile("ldmatrix.sync.aligned.m8n8.x4.trans.shared.b16 {%0,%1,%2,%3},[%4];\n"
                 : "=r"(r0), "=r"(r1), "=r"(r2), "=r"(r3) : "r"(a));
}
__device__ __forceinline__ void mma16816(float* c, const uint32_t* a,
                                         const uint32_t* b) {
    asm volatile(
        "mma.sync.aligned.m16n8k16.row.col.f32.bf16.bf16.f32 "
        "{%0,%1,%2,%3},{%4,%5,%6,%7},{%8,%9},{%0,%1,%2,%3};\n"
        : "+f"(c[0]), "+f"(c[1]), "+f"(c[2]), "+f"(c[3])
        : "r"(a[0]), "r"(a[1]), "r"(a[2]), "r"(a[3]), "r"(b[0]), "r"(b[1]));
}
// split two fp32 into packed bf16x2 hi and lo words (lo half = first element)
__device__ __forceinline__ void split2(float a, float b,
                                       uint32_t& h, uint32_t& l) {
    __nv_bfloat16 ha = __float2bfloat16(a), hb = __float2bfloat16(b);
    __nv_bfloat16 la = __float2bfloat16(a - __bfloat162float(ha));
    __nv_bfloat16 lb = __float2bfloat16(b - __bfloat162float(hb));
    h = ((uint32_t)__bfloat16_as_ushort(hb) << 16) | __bfloat16_as_ushort(ha);
    l = ((uint32_t)__bfloat16_as_ushort(lb) << 16) | __bfloat16_as_ushort(la);
}

// ---------------------------------------------------------------------------
// fp32 -> (bf16 hi, bf16 lo) split, vectorized
// ---------------------------------------------------------------------------
__global__ void split_kernel(const float* __restrict__ src,
                             __nv_bfloat16* __restrict__ hi,
                             __nv_bfloat16* __restrict__ lo, int n4)
{
    int i = blockIdx.x * blockDim.x + threadIdx.x;
    if (i >= n4) return;
    float4 v = ((const float4*)src)[i];
    uint32_t h0, l0, h1, l1;
    split2(v.x, v.y, h0, l0);
    split2(v.z, v.w, h1, l1);
    uint2 hv = make_uint2(h0, h1);
    uint2 lv = make_uint2(l0, l1);
    ((uint2*)hi)[i] = hv;
    ((uint2*)lo)[i] = lv;
}

// ---------------------------------------------------------------------------
// Tensor-core GEMM with bf16-split fp32 emulation.
// C = Ah*Bh + Ah*Bl + Al*Bh + bias (fp32 accum).
// SPLIT=false: fp32 C out.  SPLIT=true: bf16 hi/lo C out.
// ---------------------------------------------------------------------------
#define BM 128
#define BN 128
#define BKK 32
#define ALD (BKK + 8)
#define BLD (BN + 8)
#define OFF_AH 0
#define OFF_AL (BM * ALD)
#define OFF_BH (2 * BM * ALD)
#define OFF_BL (2 * BM * ALD + BKK * BLD)
#define STAGE_H (2 * BM * ALD + 2 * BKK * BLD)
#define GEMM_SMEM (2 * STAGE_H * 2)

template <bool SPLIT>
__global__ __launch_bounds__(256, 1) void bsgemm(
    int M, int N, int K,
    const __nv_bfloat16* __restrict__ Ah, const __nv_bfloat16* __restrict__ Al,
    const __nv_bfloat16* __restrict__ Bh, const __nv_bfloat16* __restrict__ Bl,
    const float* __restrict__ bias, float* __restrict__ C,
    __nv_bfloat16* __restrict__ Ch, __nv_bfloat16* __restrict__ Cl)
{
    extern __shared__ __nv_bfloat16 sm[];
    const int tid = threadIdx.x;
    const int bm = blockIdx.y, bn = blockIdx.x;
    const int wid = tid >> 5, lane = tid & 31;
    const int wm = (wid >> 2) * 64, wn = (wid & 3) * 32;

    const uint32_t smem_base = (uint32_t)__cvta_generic_to_shared(sm);

    float acc[4][4][4];
    #pragma unroll
    for (int mi = 0; mi < 4; mi++)
        #pragma unroll
        for (int nj = 0; nj < 4; nj++)
            #pragma unroll
            for (int r = 0; r < 4; r++) acc[mi][nj][r] = 0.f;

    const int NK = K / BKK;

    auto load_stage = [&](int s, int kt) {
        const uint32_t base = smem_base + s * (STAGE_H * 2);
        const int k0 = kt * BKK;
        #pragma unroll
        for (int i = 0; i < 2; i++) {
            int idx = tid + i * 256;
            int r  = idx >> 2, c  = (idx & 3) << 3;
            size_t aoff = (size_t)(bm * BM + r) * K + k0 + c;
            cp16(base + (OFF_AH + r * ALD + c) * 2, Ah + aoff);
            cp16(base + (OFF_AL + r * ALD + c) * 2, Al + aoff);
            int rb = idx >> 4, cb = (idx & 15) << 3;
            size_t boff = (size_t)(k0 + rb) * N + bn * BN + cb;
            cp16(base + (OFF_BH + rb * BLD + cb) * 2, Bh + boff);
            cp16(base + (OFF_BL + rb * BLD + cb) * 2, Bl + boff);
        }
        asm volatile("cp.async.commit_group;\n");
    };

    load_stage(0, 0);

    for (int kt = 0; kt < NK; kt++) {
        if (kt + 1 < NK) {
            load_stage((kt + 1) & 1, kt + 1);
            asm volatile("cp.async.wait_group 1;\n");
        } else {
            asm volatile("cp.async.wait_group 0;\n");
        }
        __syncthreads();

        const uint32_t base = smem_base + (kt & 1) * (STAGE_H * 2);

        #pragma unroll
        for (int ks = 0; ks < 2; ks++) {
            const int k = ks * 16;
            uint32_t ah[4][4], al[4][4];
            #pragma unroll
            for (int mi = 0; mi < 4; mi++) {
                int row = wm + mi * 16 + (lane & 15);
                int col = k + (lane >> 4) * 8;
                ldsm4(ah[mi][0], ah[mi][1], ah[mi][2], ah[mi][3],
                      base + (OFF_AH + row * ALD + col) * 2);
                ldsm4(al[mi][0], al[mi][1], al[mi][2], al[mi][3],
                      base + (OFF_AL + row * ALD + col) * 2);
            }
            uint32_t bh[2][4], bl[2][4];
            #pragma unroll
            for (int ng = 0; ng < 2; ng++) {
                int row = k + (lane & 15);
                int col = wn + ng * 16 + (lane >> 4) * 8;
                ldsm4t(bh[ng][0], bh[ng][1], bh[ng][2], bh[ng][3],
                       base + (OFF_BH + row * BLD + col) * 2);
                ldsm4t(bl[ng][0], bl[ng][1], bl[ng][2], bl[ng][3],
                       base + (OFF_BL + row * BLD + col) * 2);
            }
            #pragma unroll
            for (int mi = 0; mi < 4; mi++) {
                #pragma unroll
                for (int nj = 0; nj < 4; nj++) {
                    const uint32_t* bhp = &bh[nj >> 1][(nj & 1) * 2];
                    const uint32_t* blp = &bl[nj >> 1][(nj & 1) * 2];
                    mma16816(acc[mi][nj], ah[mi], bhp);
                    mma16816(acc[mi][nj], ah[mi], blp);
                    mma16816(acc[mi][nj], al[mi], bhp);
                }
            }
        }
        __syncthreads();
    }

    #pragma unroll
    for (int mi = 0; mi < 4; mi++) {
        #pragma unroll
        for (int nj = 0; nj < 4; nj++) {
            int r0 = bm * BM + wm + mi * 16 + (lane >> 2);
            int c0 = bn * BN + wn + nj * 8 + (lane & 3) * 2;
            float b0 = bias[c0], b1 = bias[c0 + 1];
            float v00 = acc[mi][nj][0] + b0, v01 = acc[mi][nj][1] + b1;
            float v10 = acc[mi][nj][2] + b0, v11 = acc[mi][nj][3] + b1;
            if (SPLIT) {
                uint32_t hp, lp;
                split2(v00, v01, hp, lp);
                *(uint32_t*)&Ch[(size_t)r0 * N + c0] = hp;
                *(uint32_t*)&Cl[(size_t)r0 * N + c0] = lp;
                split2(v10, v11, hp, lp);
                *(uint32_t*)&Ch[(size_t)(r0 + 8) * N + c0] = hp;
                *(uint32_t*)&Cl[(size_t)(r0 + 8) * N + c0] = lp;
            } else {
                *(float2*)&C[(size_t)r0 * N + c0]       = make_float2(v00, v01);
                *(float2*)&C[(size_t)(r0 + 8) * N + c0] = make_float2(v10, v11);
            }
        }
    }
}

// ---------------------------------------------------------------------------
// Tensor-core flash attention. CTA = (64-query block, head, batch), 4 warps.
// Warp owns 16 query rows. S = QK^T and O += PV via bf16 hi/lo split mma.
// K/V double-buffered cp.async.
// ---------------------------------------------------------------------------
#define AP 72                                 // padded row halves (144B)
#define ATT_SQH 0
#define ATT_SQL (64 * AP)
#define ATT_STAGE0 (2 * 64 * AP)              // 9216 halves
#define ATT_STAGE_SZ (4 * 64 * AP)            // 18432 halves
#define ATT_KH 0
#define ATT_KL (64 * AP)
#define ATT_VH (2 * 64 * AP)
#define ATT_VL (3 * 64 * AP)
#define ATT_SMEM ((2 * 64 * AP + 2 * 4 * 64 * AP) * 2)   // 92160 bytes

__global__ __launch_bounds__(128) void attn_tc(
    const __nv_bfloat16* __restrict__ qh_g,
    const __nv_bfloat16* __restrict__ ql_g,
    __nv_bfloat16* __restrict__ ctxh,
    __nv_bfloat16* __restrict__ ctxl)
{
    extern __shared__ __nv_bfloat16 smb[];
    const uint32_t sb = (uint32_t)__cvta_generic_to_shared(smb);
    const int qb = blockIdx.x, h = blockIdx.y, b = blockIdx.z;
    const int qs = qb * 64;
    const bool isg = (h < NGLOBAL);
    const int tid = threadIdx.x, lane = tid & 31, warp = tid >> 5;
    const int wq = warp * 16;
    const size_t rowbase = (size_t)(b * SEQ) * QKV_N;
    const float NEG_INF = __int_as_float(0xff800000u);

    // Q loads (hi+lo), group 1
    #pragma unroll
    for (int i = 0; i < 4; i++) {
        int idx = tid + i * 128;
        int r = idx >> 3, c8 = (idx & 7) * 8;
        size_t src = rowbase + (size_t)(qs + r) * QKV_N + h * HDIM + c8;
        cp16(sb + (ATT_SQH + r * AP + c8) * 2, qh_g + src);
        cp16(sb + (ATT_SQL + r * AP + c8) * 2, ql_g + src);
    }
    asm volatile("cp.async.commit_group;\n");

    const int kb0 = isg ? 0 : max(0, qb - 4);

    auto load_kv = [&](int kb, int s) {
        const uint32_t base = sb + (ATT_STAGE0 + s * ATT_STAGE_SZ) * 2;
        const int ks = kb * 64;
        #pragma unroll
        for (int i = 0; i < 4; i++) {
            int idx = tid + i * 128;
            int r = idx >> 3, c8 = (idx & 7) * 8;
            size_t src = rowbase + (size_t)(ks + r) * QKV_N + EMBED + h * HDIM + c8;
            cp16(base + (ATT_KH + r * AP + c8) * 2, qh_g + src);
            cp16(base + (ATT_KL + r * AP + c8) * 2, ql_g + src);
            cp16(base + (ATT_VH + r * AP + c8) * 2, qh_g + src + EMBED);
            cp16(base + (ATT_VL + r * AP + c8) * 2, ql_g + src + EMBED);
        }
        asm volatile("cp.async.commit_group;\n");
    };

    load_kv(kb0, 0);

    float m0 = -1e30f, m1 = -1e30f, l0 = 0.f, l1 = 0.f;
    float O[8][4];
    #pragma unroll
    for (int nj = 0; nj < 8; nj++)
        #pragma unroll
        for (int r = 0; r < 4; r++) O[nj][r] = 0.f;

    uint32_t qfh[4][4], qfl[4][4];
    bool qloaded = false;

    for (int kb = kb0; kb <= qb; kb++) {
        const int s = (kb - kb0) & 1;
        const int ks = kb * 64;
        __syncthreads();                       // all done reading stage s (from kb-2)
        if (kb < qb) {
            load_kv(kb + 1, s ^ 1);
            asm volatile("cp.async.wait_group 1;\n");
        } else {
            asm volatile("cp.async.wait_group 0;\n");
        }
        __syncthreads();                       // stage s (and Q) visible to all

        if (!qloaded) {
            qloaded = true;
            #pragma unroll
            for (int kt = 0; kt < 4; kt++) {
                uint32_t a = sb + (ATT_SQH + (wq + (lane & 15)) * AP
                                   + kt * 16 + 8 * (lane >> 4)) * 2;
                ldsm4(qfh[kt][0], qfh[kt][1], qfh[kt][2], qfh[kt][3], a);
                ldsm4(qfl[kt][0], qfl[kt][1], qfl[kt][2], qfl[kt][3],
                      a + (ATT_SQL - ATT_SQH) * 2);
            }
        }

        const uint32_t kbase = sb + (ATT_STAGE0 + s * ATT_STAGE_SZ) * 2;

        // ---- S = Q K^T (hi/lo split) ----
        float sf[8][4];
        #pragma unroll
        for (int nj = 0; nj < 8; nj++)
            #pragma unroll
            for (int r = 0; r < 4; r++) sf[nj][r] = 0.f;

        #pragma unroll
        for (int kt = 0; kt < 4; kt++) {
            #pragma unroll
            for (int ng = 0; ng < 4; ng++) {
                uint32_t kh[4], kl[4];
                uint32_t a = kbase + ((ng * 16 + (lane & 15)) * AP
                                      + kt * 16 + 8 * (lane >> 4)) * 2;
                ldsm4(kh[0], kh[1], kh[2], kh[3], a + ATT_KH * 2);
                ldsm4(kl[0], kl[1], kl[2], kl[3], a + ATT_KL * 2);
                uint32_t bh0[2] = {kh[0], kh[2]}, bh1[2] = {kh[1], kh[3]};
                uint32_t bl0[2] = {kl[0], kl[2]}, bl1[2] = {kl[1], kl[3]};
                mma16816(sf[2 * ng],     qfh[kt], bh0);
                mma16816(sf[2 * ng],     qfh[kt], bl0);
                mma16816(sf[2 * ng],     qfl[kt], bh0);
                mma16816(sf[2 * ng + 1], qfh[kt], bh1);
                mma16816(sf[2 * ng + 1], qfh[kt], bl1);
                mma16816(sf[2 * ng + 1], qfl[kt], bh1);
            }
        }
        #pragma unroll
        for (int nj = 0; nj < 8; nj++)
            #pragma unroll
            for (int r = 0; r < 4; r++) sf[nj][r] *= 0.125f;

        // ---- mask (diag block: causal; window-edge block: i-j<=WINDOW) ----
        const int i0 = qs + wq + (lane >> 2);
        const int i1 = i0 + 8;
        const int mode = (kb == qb) ? 1 : ((!isg && (qb - kb) == 4) ? 2 : 0);
        if (mode == 1) {
            #pragma unroll
            for (int nj = 0; nj < 8; nj++) {
                int j0 = ks + nj * 8 + (lane & 3) * 2, j1 = j0 + 1;
                if (j0 > i0) sf[nj][0] = NEG_INF;
                if (j1 > i0) sf[nj][1] = NEG_INF;
                if (j0 > i1) sf[nj][2] = NEG_INF;
                if (j1 > i1) sf[nj][3] = NEG_INF;
            }
        } else if (mode == 2) {
            #pragma unroll
            for (int nj = 0; nj < 8; nj++) {
                int j0 = ks + nj * 8 + (lane & 3) * 2, j1 = j0 + 1;
                if (i0 - j0 > WINDOW) sf[nj][0] = NEG_INF;
                if (i0 - j1 > WINDOW) sf[nj][1] = NEG_INF;
                if (i1 - j0 > WINDOW) sf[nj][2] = NEG_INF;
                if (i1 - j1 > WINDOW) sf[nj][3] = NEG_INF;
            }
        }

        // ---- online softmax ----
        float mx0 = -1e30f, mx1 = -1e30f;
        #pragma unroll
        for (int nj = 0; nj < 8; nj++) {
            mx0 = fmaxf(mx0, fmaxf(sf[nj][0], sf[nj][1]));
            mx1 = fmaxf(mx1, fmaxf(sf[nj][2], sf[nj][3]));
        }
        mx0 = fmaxf(mx0, __shfl_xor_sync(0xffffffffu, mx0, 1));
        mx0 = fmaxf(mx0, __shfl_xor_sync(0xffffffffu, mx0, 2));
        mx1 = fmaxf(mx1, __shfl_xor_sync(0xffffffffu, mx1, 1));
        mx1 = fmaxf(mx1, __shfl_xor_sync(0xffffffffu, mx1, 2));
        const float mn0 = fmaxf(m0, mx0), mn1 = fmaxf(m1, mx1);
        float s0 = 0.f, s1 = 0.f;
        #pragma unroll
        for (int nj = 0; nj < 8; nj++) {
            sf[nj][0] = __expf(sf[nj][0] - mn0);
            sf[nj][1] = __expf(sf[nj][1] - mn0);
            sf[nj][2] = __expf(sf[nj][2] - mn1);
            sf[nj][3] = __expf(sf[nj][3] - mn1);
            s0 += sf[nj][0] + sf[nj][1];
            s1 += sf[nj][2] + sf[nj][3];
        }
        s0 += __shfl_xor_sync(0xffffffffu, s0, 1);
        s0 += __shfl_xor_sync(0xffffffffu, s0, 2);
        s1 += __shfl_xor_sync(0xffffffffu, s1, 1);
        s1 += __shfl_xor_sync(0xffffffffu, s1, 2);
        const float a0 = __expf(m0 - mn0), a1 = __expf(m1 - mn1);
        l0 = l0 * a0 + s0; l1 = l1 * a1 + s1;
        m0 = mn0; m1 = mn1;
        #pragma unroll
        for (int nj = 0; nj < 8; nj++) {
            O[nj][0] *= a0; O[nj][1] *= a0;
            O[nj][2] *= a1; O[nj][3] *= a1;
        }

        // ---- O += P V (P split hi/lo from fragments) ----
        #pragma unroll
        for (int kt = 0; kt < 4; kt++) {
            uint32_t pah[4], pal[4];
            split2(sf[2 * kt][0],     sf[2 * kt][1],     pah[0], pal[0]);
            split2(sf[2 * kt][2],     sf[2 * kt][3],     pah[1], pal[1]);
            split2(sf[2 * kt + 1][0], sf[2 * kt + 1][1], pah[2], pal[2]);
            split2(sf[2 * kt + 1][2], sf[2 * kt + 1][3], pah[3], pal[3]);
            #pragma unroll
            for (int ng = 0; ng < 4; ng++) {
                uint32_t vh[4], vl[4];
                uint32_t a = kbase + ((kt * 16 + (lane & 15)) * AP
                                      + ng * 16 + 8 * (lane >> 4)) * 2;
                ldsm4t(vh[0], vh[1], vh[2], vh[3], a + ATT_VH * 2);
                ldsm4t(vl[0], vl[1], vl[2], vl[3], a + ATT_VL * 2);
                mma16816(O[2 * ng],     pah, &vh[0]);
                mma16816(O[2 * ng],     pah, &vl[0]);
                mma16816(O[2 * ng],     pal, &vh[0]);
                mma16816(O[2 * ng + 1], pah, &vh[2]);
                mma16816(O[2 * ng + 1], pah, &vl[2]);
                mma16816(O[2 * ng + 1], pal, &vh[2]);
            }
        }
    }

    // ---- epilogue: normalize, split to bf16 hi/lo ctx ----
    const float inv0 = 1.f / l0, inv1 = 1.f / l1;
    const int r0g = qs + wq + (lane >> 2);
    const size_t base0 = ((size_t)(b * SEQ + r0g)) * EMBED + h * HDIM;
    #pragma unroll
    for (int nj = 0; nj < 8; nj++) {
        const int c = nj * 8 + (lane & 3) * 2;
        uint32_t hp, lp;
        split2(O[nj][0] * inv0, O[nj][1] * inv0, hp, lp);
        *(uint32_t*)&ctxh[base0 + c] = hp;
        *(uint32_t*)&ctxl[base0 + c] = lp;
        split2(O[nj][2] * inv1, O[nj][3] * inv1, hp, lp);
        *(uint32_t*)&ctxh[base0 + (size_t)8 * EMBED + c] = hp;
        *(uint32_t*)&ctxl[base0 + (size_t)8 * EMBED + c] = lp;
    }
}

// ---------------------------------------------------------------------------
// Launch
// ---------------------------------------------------------------------------
extern "C" void kernel_launch(void* const* d_in, const int* in_sizes, int n_in,
                              void* d_out, int out_size)
{
    const float* x     = (const float*)d_in[0];
    const float* w_qkv = (const float*)d_in[1];
    const float* b_qkv = (const float*)d_in[2];
    const float* w_out = (const float*)d_in[3];
    const float* b_out = (const float*)d_in[4];
    float* out = (float*)d_out;

    __nv_bfloat16 *qkvh, *qkvl, *xh, *xl, *wqh, *wql, *woh, *wol, *ctxh, *ctxl;
    cudaGetSymbolAddress((void**)&qkvh, g_qkvh);
    cudaGetSymbolAddress((void**)&qkvl, g_qkvl);
    cudaGetSymbolAddress((void**)&xh,  g_xh);
    cudaGetSymbolAddress((void**)&xl,  g_xl);
    cudaGetSymbolAddress((void**)&wqh, g_wqh);
    cudaGetSymbolAddress((void**)&wql, g_wql);
    cudaGetSymbolAddress((void**)&woh, g_woh);
    cudaGetSymbolAddress((void**)&wol, g_wol);
    cudaGetSymbolAddress((void**)&ctxh, g_ctxh);
    cudaGetSymbolAddress((void**)&ctxl, g_ctxl);

    cudaFuncSetAttribute(bsgemm<true>,  cudaFuncAttributeMaxDynamicSharedMemorySize, GEMM_SMEM);
    cudaFuncSetAttribute(bsgemm<false>, cudaFuncAttributeMaxDynamicSharedMemorySize, GEMM_SMEM);
    cudaFuncSetAttribute(attn_tc, cudaFuncAttributeMaxDynamicSharedMemorySize, ATT_SMEM);

    // 0) Splits: x, w_qkv, w_out -> bf16 hi/lo
    {
        int n4;
        n4 = MROWS * EMBED / 4;
        split_kernel<<<(n4 + 255) / 256, 256>>>(x, xh, xl, n4);
        n4 = EMBED * QKV_N / 4;
        split_kernel<<<(n4 + 255) / 256, 256>>>(w_qkv, wqh, wql, n4);
        n4 = EMBED * EMBED / 4;
        split_kernel<<<(n4 + 255) / 256, 256>>>(w_out, woh, wol, n4);
    }

    // 1) QKV projection -> bf16 hi/lo qkv
    {
        dim3 grid(QKV_N / BN, MROWS / BM);
        bsgemm<true><<<grid, 256, GEMM_SMEM>>>(MROWS, QKV_N, EMBED,
                                               xh, xl, wqh, wql, b_qkv,
                                               nullptr, qkvh, qkvl);
    }
    // 2) Tensor-core attention -> bf16 hi/lo ctx
    {
        dim3 grid(SEQ / 64, HEADS, BATCH);
        attn_tc<<<grid, 128, ATT_SMEM>>>(qkvh, qkvl, ctxh, ctxl);
    }
    // 3) Output projection -> fp32 out
    {
        dim3 grid(EMBED / BN, MROWS / BM);
        bsgemm<false><<<grid, 256, GEMM_SMEM>>>(MROWS, EMBED, EMBED,
                                                ctxh, ctxl, woh, wol, b_out,
                                                out, nullptr, nullptr);
    }
}

// round 7
// speedup vs baseline: 3.3287x; 1.3710x over previous
#include <cuda_runtime.h>
#include <cuda_bf16.h>
#include <cuda_fp16.h>
#include <cstdint>

#define BATCH   4
#define SEQ     2048
#define EMBED   1024
#define HEADS   16
#define HDIM    64
#define NGLOBAL 4
#define WINDOW  256

#define MROWS   (BATCH * SEQ)          // 8192
#define QKV_N   (3 * EMBED)            // 3072

// ---------------------------------------------------------------------------
// Scratch (device globals: allocation-guard-safe)
// ---------------------------------------------------------------------------
__device__ __nv_bfloat16 g_qkvh[(size_t)MROWS * QKV_N];   // bf16 hi (attn input)
__device__ __nv_bfloat16 g_qkvl[(size_t)MROWS * QKV_N];   // bf16 lo
__device__ __half        g_xh  [(size_t)MROWS * EMBED];   // fp16 hi
__device__ __half        g_xl  [(size_t)MROWS * EMBED];   // fp16 lo
__device__ __half        g_wq16[(size_t)EMBED * QKV_N];   // fp16 weights
__device__ __half        g_wo16[(size_t)EMBED * EMBED];
__device__ __half        g_ctxh[(size_t)MROWS * EMBED];   // fp16 hi
__device__ __half        g_ctxl[(size_t)MROWS * EMBED];   // fp16 lo

// ---------------------------------------------------------------------------
// Helpers
// ---------------------------------------------------------------------------
__device__ __forceinline__ void cp16(uint32_t dst, const void* src) {
    asm volatile("cp.async.cg.shared.global [%0], [%1], 16;\n"
                 :: "r"(dst), "l"(src));
}
__device__ __forceinline__ void ldsm4(uint32_t& r0, uint32_t& r1,
                                      uint32_t& r2, uint32_t& r3, uint32_t a) {
    asm volatile("ldmatrix.sync.aligned.m8n8.x4.shared.b16 {%0,%1,%2,%3},[%4];\n"
                 : "=r"(r0), "=r"(r1), "=r"(r2), "=r"(r3) : "r"(a));
}
__device__ __forceinline__ void ldsm4t(uint32_t& r0, uint32_t& r1,
                                       uint32_t& r2, uint32_t& r3, uint32_t a) {
    asm volatile("ldmatrix.sync.aligned.m8n8.x4.trans.shared.b16 {%0,%1,%2,%3},[%4];\n"
                 : "=r"(r0), "=r"(r1), "=r"(r2), "=r"(r3) : "r"(a));
}
// bf16 mma (attention)
__device__ __forceinline__ void mma16816(float* c, const uint32_t* a,
                                         const uint32_t* b) {
    asm volatile(
        "mma.sync.aligned.m16n8k16.row.col.f32.bf16.bf16.f32 "
        "{%0,%1,%2,%3},{%4,%5,%6,%7},{%8,%9},{%0,%1,%2,%3};\n"
        : "+f"(c[0]), "+f"(c[1]), "+f"(c[2]), "+f"(c[3])
        : "r"(a[0]), "r"(a[1]), "r"(a[2]), "r"(a[3]), "r"(b[0]), "r"(b[1]));
}
// fp16 mma (projections)
__device__ __forceinline__ void mma16816h(float* c, const uint32_t* a,
                                          const uint32_t* b) {
    asm volatile(
        "mma.sync.aligned.m16n8k16.row.col.f32.f16.f16.f32 "
        "{%0,%1,%2,%3},{%4,%5,%6,%7},{%8,%9},{%0,%1,%2,%3};\n"
        : "+f"(c[0]), "+f"(c[1]), "+f"(c[2]), "+f"(c[3])
        : "r"(a[0]), "r"(a[1]), "r"(a[2]), "r"(a[3]), "r"(b[0]), "r"(b[1]));
}
// bf16 hi/lo packed split
__device__ __forceinline__ void split2(float a, float b,
                                       uint32_t& h, uint32_t& l) {
    __nv_bfloat16 ha = __float2bfloat16(a), hb = __float2bfloat16(b);
    __nv_bfloat16 la = __float2bfloat16(a - __bfloat162float(ha));
    __nv_bfloat16 lb = __float2bfloat16(b - __bfloat162float(hb));
    h = ((uint32_t)__bfloat16_as_ushort(hb) << 16) | __bfloat16_as_ushort(ha);
    l = ((uint32_t)__bfloat16_as_ushort(lb) << 16) | __bfloat16_as_ushort(la);
}
// fp16 hi/lo packed split
__device__ __forceinline__ void split2h(float a, float b,
                                        uint32_t& h, uint32_t& l) {
    __half ha = __float2half_rn(a), hb = __float2half_rn(b);
    __half la = __float2half_rn(a - __half2float(ha));
    __half lb = __float2half_rn(b - __half2float(hb));
    h = ((uint32_t)__half_as_ushort(hb) << 16) | __half_as_ushort(ha);
    l = ((uint32_t)__half_as_ushort(lb) << 16) | __half_as_ushort(la);
}

// ---------------------------------------------------------------------------
// fp32 -> fp16 hi/lo split (activations)
// ---------------------------------------------------------------------------
__global__ void splith_kernel(const float* __restrict__ src,
                              __half* __restrict__ hi,
                              __half* __restrict__ lo, int n4)
{
    int i = blockIdx.x * blockDim.x + threadIdx.x;
    if (i >= n4) return;
    float4 v = ((const float4*)src)[i];
    uint32_t h0, l0, h1, l1;
    split2h(v.x, v.y, h0, l0);
    split2h(v.z, v.w, h1, l1);
    ((uint2*)hi)[i] = make_uint2(h0, h1);
    ((uint2*)lo)[i] = make_uint2(l0, l1);
}

// fp32 -> fp16 convert (weights)
__global__ void cvth_kernel(const float* __restrict__ src,
                            __half* __restrict__ dst, int n4)
{
    int i = blockIdx.x * blockDim.x + threadIdx.x;
    if (i >= n4) return;
    float4 v = ((const float4*)src)[i];
    __half2 a = __floats2half2_rn(v.x, v.y);
    __half2 b = __floats2half2_rn(v.z, v.w);
    ((uint2*)dst)[i] = make_uint2(*(uint32_t*)&a, *(uint32_t*)&b);
}

// ---------------------------------------------------------------------------
// fp16 tensor-core GEMM, 2-term split: C = (Ah+Al) @ B + bias, fp32 accum.
// 128x128x32 CTA tile, 8 warps (64x32 warp tiles), 3-stage cp.async ring,
// one __syncthreads per K-iter, 2 CTAs/SM.
// SPLIT=false: fp32 C.  SPLIT=true: bf16 hi/lo C.
// ---------------------------------------------------------------------------
#define BM 128
#define BN 128
#define BKK 32
#define NSTAGE 3
#define ALD (BKK + 8)                      // 40
#define BLD (BN + 8)                       // 136
#define OFF_AH 0
#define OFF_AL (BM * ALD)                  // 5120
#define OFF_B  (2 * BM * ALD)              // 10240
#define STAGE_H (2 * BM * ALD + BKK * BLD) // 14592 halves
#define GEMM_SMEM (NSTAGE * STAGE_H * 2)   // 87552 bytes

template <bool SPLIT>
__global__ __launch_bounds__(256, 2) void hsgemm(
    int M, int N, int K,
    const __half* __restrict__ Ah, const __half* __restrict__ Al,
    const __half* __restrict__ B16,
    const float* __restrict__ bias, float* __restrict__ C,
    __nv_bfloat16* __restrict__ Ch, __nv_bfloat16* __restrict__ Cl)
{
    extern __shared__ __half sm[];
    const int tid = threadIdx.x;
    const int bm = blockIdx.y, bn = blockIdx.x;
    const int wid = tid >> 5, lane = tid & 31;
    const int wm = (wid >> 2) * 64, wn = (wid & 3) * 32;

    const uint32_t smem_base = (uint32_t)__cvta_generic_to_shared(sm);

    float acc[4][4][4];
    #pragma unroll
    for (int mi = 0; mi < 4; mi++)
        #pragma unroll
        for (int nj = 0; nj < 4; nj++)
            #pragma unroll
            for (int r = 0; r < 4; r++) acc[mi][nj][r] = 0.f;

    const int NK = K / BKK;

    auto load_stage = [&](int s, int kt) {
        const uint32_t base = smem_base + s * (STAGE_H * 2);
        const int k0 = kt * BKK;
        #pragma unroll
        for (int i = 0; i < 2; i++) {
            int idx = tid + i * 256;                   // 0..511
            int r = idx >> 2, c = (idx & 3) << 3;      // A: 128 x 4 chunks
            size_t aoff = (size_t)(bm * BM + r) * K + k0 + c;
            cp16(base + (OFF_AH + r * ALD + c) * 2, Ah + aoff);
            cp16(base + (OFF_AL + r * ALD + c) * 2, Al + aoff);
            int rb = idx >> 4, cb = (idx & 15) << 3;   // B: 32 x 16 chunks
            size_t boff = (size_t)(k0 + rb) * N + bn * BN + cb;
            cp16(base + (OFF_B + rb * BLD + cb) * 2, B16 + boff);
        }
        asm volatile("cp.async.commit_group;\n");
    };

    load_stage(0, 0);
    if (NK > 1) load_stage(1, 1);

    for (int kt = 0; kt < NK; kt++) {
        if (kt + 1 < NK) asm volatile("cp.async.wait_group 1;\n");
        else             asm volatile("cp.async.wait_group 0;\n");
        __syncthreads();
        if (kt + 2 < NK) load_stage((kt + 2) % NSTAGE, kt + 2);

        const uint32_t base = smem_base + (kt % NSTAGE) * (STAGE_H * 2);

        #pragma unroll
        for (int ks = 0; ks < 2; ks++) {
            const int k = ks * 16;
            uint32_t ah[4][4], al[4][4];
            #pragma unroll
            for (int mi = 0; mi < 4; mi++) {
                int row = wm + mi * 16 + (lane & 15);
                int col = k + (lane >> 4) * 8;
                ldsm4(ah[mi][0], ah[mi][1], ah[mi][2], ah[mi][3],
                      base + (OFF_AH + row * ALD + col) * 2);
                ldsm4(al[mi][0], al[mi][1], al[mi][2], al[mi][3],
                      base + (OFF_AL + row * ALD + col) * 2);
            }
            uint32_t bh[2][4];
            #pragma unroll
            for (int ng = 0; ng < 2; ng++) {
                int row = k + (lane & 15);
                int col = wn + ng * 16 + (lane >> 4) * 8;
                ldsm4t(bh[ng][0], bh[ng][1], bh[ng][2], bh[ng][3],
                       base + (OFF_B + row * BLD + col) * 2);
            }
            #pragma unroll
            for (int mi = 0; mi < 4; mi++) {
                #pragma unroll
                for (int nj = 0; nj < 4; nj++) {
                    const uint32_t* bp = &bh[nj >> 1][(nj & 1) * 2];
                    mma16816h(acc[mi][nj], ah[mi], bp);
                    mma16816h(acc[mi][nj], al[mi], bp);
                }
            }
        }
    }

    #pragma unroll
    for (int mi = 0; mi < 4; mi++) {
        #pragma unroll
        for (int nj = 0; nj < 4; nj++) {
            int r0 = bm * BM + wm + mi * 16 + (lane >> 2);
            int c0 = bn * BN + wn + nj * 8 + (lane & 3) * 2;
            float b0 = bias[c0], b1 = bias[c0 + 1];
            float v00 = acc[mi][nj][0] + b0, v01 = acc[mi][nj][1] + b1;
            float v10 = acc[mi][nj][2] + b0, v11 = acc[mi][nj][3] + b1;
            if (SPLIT) {
                uint32_t hp, lp;
                split2(v00, v01, hp, lp);
                *(uint32_t*)&Ch[(size_t)r0 * N + c0] = hp;
                *(uint32_t*)&Cl[(size_t)r0 * N + c0] = lp;
                split2(v10, v11, hp, lp);
                *(uint32_t*)&Ch[(size_t)(r0 + 8) * N + c0] = hp;
                *(uint32_t*)&Cl[(size_t)(r0 + 8) * N + c0] = lp;
            } else {
                *(float2*)&C[(size_t)r0 * N + c0]       = make_float2(v00, v01);
                *(float2*)&C[(size_t)(r0 + 8) * N + c0] = make_float2(v10, v11);
            }
        }
    }
}

// ---------------------------------------------------------------------------
// Tensor-core flash attention (bf16 3-term, unchanged from R5 except ctx
// epilogue emits fp16 hi/lo for the fp16 output projection).
// ---------------------------------------------------------------------------
#define AP 72
#define ATT_SQH 0
#define ATT_SQL (64 * AP)
#define ATT_STAGE0 (2 * 64 * AP)
#define ATT_STAGE_SZ (4 * 64 * AP)
#define ATT_KH 0
#define ATT_KL (64 * AP)
#define ATT_VH (2 * 64 * AP)
#define ATT_VL (3 * 64 * AP)
#define ATT_SMEM ((2 * 64 * AP + 2 * 4 * 64 * AP) * 2)

__global__ __launch_bounds__(128) void attn_tc(
    const __nv_bfloat16* __restrict__ qh_g,
    const __nv_bfloat16* __restrict__ ql_g,
    __half* __restrict__ ctxh,
    __half* __restrict__ ctxl)
{
    extern __shared__ __nv_bfloat16 smb[];
    const uint32_t sb = (uint32_t)__cvta_generic_to_shared(smb);
    const int qb = blockIdx.x, h = blockIdx.y, b = blockIdx.z;
    const int qs = qb * 64;
    const bool isg = (h < NGLOBAL);
    const int tid = threadIdx.x, lane = tid & 31, warp = tid >> 5;
    const int wq = warp * 16;
    const size_t rowbase = (size_t)(b * SEQ) * QKV_N;
    const float NEG_INF = __int_as_float(0xff800000u);

    #pragma unroll
    for (int i = 0; i < 4; i++) {
        int idx = tid + i * 128;
        int r = idx >> 3, c8 = (idx & 7) * 8;
        size_t src = rowbase + (size_t)(qs + r) * QKV_N + h * HDIM + c8;
        cp16(sb + (ATT_SQH + r * AP + c8) * 2, qh_g + src);
        cp16(sb + (ATT_SQL + r * AP + c8) * 2, ql_g + src);
    }
    asm volatile("cp.async.commit_group;\n");

    const int kb0 = isg ? 0 : max(0, qb - 4);

    auto load_kv = [&](int kb, int s) {
        const uint32_t base = sb + (ATT_STAGE0 + s * ATT_STAGE_SZ) * 2;
        const int ks = kb * 64;
        #pragma unroll
        for (int i = 0; i < 4; i++) {
            int idx = tid + i * 128;
            int r = idx >> 3, c8 = (idx & 7) * 8;
            size_t src = rowbase + (size_t)(ks + r) * QKV_N + EMBED + h * HDIM + c8;
            cp16(base + (ATT_KH + r * AP + c8) * 2, qh_g + src);
            cp16(base + (ATT_KL + r * AP + c8) * 2, ql_g + src);
            cp16(base + (ATT_VH + r * AP + c8) * 2, qh_g + src + EMBED);
            cp16(base + (ATT_VL + r * AP + c8) * 2, ql_g + src + EMBED);
        }
        asm volatile("cp.async.commit_group;\n");
    };

    load_kv(kb0, 0);

    float m0 = -1e30f, m1 = -1e30f, l0 = 0.f, l1 = 0.f;
    float O[8][4];
    #pragma unroll
    for (int nj = 0; nj < 8; nj++)
        #pragma unroll
        for (int r = 0; r < 4; r++) O[nj][r] = 0.f;

    uint32_t qfh[4][4], qfl[4][4];
    bool qloaded = false;

    for (int kb = kb0; kb <= qb; kb++) {
        const int s = (kb - kb0) & 1;
        const int ks = kb * 64;
        __syncthreads();
        if (kb < qb) {
            load_kv(kb + 1, s ^ 1);
            asm volatile("cp.async.wait_group 1;\n");
        } else {
            asm volatile("cp.async.wait_group 0;\n");
        }
        __syncthreads();

        if (!qloaded) {
            qloaded = true;
            #pragma unroll
            for (int kt = 0; kt < 4; kt++) {
                uint32_t a = sb + (ATT_SQH + (wq + (lane & 15)) * AP
                                   + kt * 16 + 8 * (lane >> 4)) * 2;
                ldsm4(qfh[kt][0], qfh[kt][1], qfh[kt][2], qfh[kt][3], a);
                ldsm4(qfl[kt][0], qfl[kt][1], qfl[kt][2], qfl[kt][3],
                      a + (ATT_SQL - ATT_SQH) * 2);
            }
        }

        const uint32_t kbase = sb + (ATT_STAGE0 + s * ATT_STAGE_SZ) * 2;

        float sf[8][4];
        #pragma unroll
        for (int nj = 0; nj < 8; nj++)
            #pragma unroll
            for (int r = 0; r < 4; r++) sf[nj][r] = 0.f;

        #pragma unroll
        for (int kt = 0; kt < 4; kt++) {
            #pragma unroll
            for (int ng = 0; ng < 4; ng++) {
                uint32_t kh[4], kl[4];
                uint32_t a = kbase + ((ng * 16 + (lane & 15)) * AP
                                      + kt * 16 + 8 * (lane >> 4)) * 2;
                ldsm4(kh[0], kh[1], kh[2], kh[3], a + ATT_KH * 2);
                ldsm4(kl[0], kl[1], kl[2], kl[3], a + ATT_KL * 2);
                uint32_t bh0[2] = {kh[0], kh[2]}, bh1[2] = {kh[1], kh[3]};
                uint32_t bl0[2] = {kl[0], kl[2]}, bl1[2] = {kl[1], kl[3]};
                mma16816(sf[2 * ng],     qfh[kt], bh0);
                mma16816(sf[2 * ng],     qfh[kt], bl0);
                mma16816(sf[2 * ng],     qfl[kt], bh0);
                mma16816(sf[2 * ng + 1], qfh[kt], bh1);
                mma16816(sf[2 * ng + 1], qfh[kt], bl1);
                mma16816(sf[2 * ng + 1], qfl[kt], bh1);
            }
        }
        #pragma unroll
        for (int nj = 0; nj < 8; nj++)
            #pragma unroll
            for (int r = 0; r < 4; r++) sf[nj][r] *= 0.125f;

        const int i0 = qs + wq + (lane >> 2);
        const int i1 = i0 + 8;
        const int mode = (kb == qb) ? 1 : ((!isg && (qb - kb) == 4) ? 2 : 0);
        if (mode == 1) {
            #pragma unroll
            for (int nj = 0; nj < 8; nj++) {
                int j0 = ks + nj * 8 + (lane & 3) * 2, j1 = j0 + 1;
                if (j0 > i0) sf[nj][0] = NEG_INF;
                if (j1 > i0) sf[nj][1] = NEG_INF;
                if (j0 > i1) sf[nj][2] = NEG_INF;
                if (j1 > i1) sf[nj][3] = NEG_INF;
            }
        } else if (mode == 2) {
            #pragma unroll
            for (int nj = 0; nj < 8; nj++) {
                int j0 = ks + nj * 8 + (lane & 3) * 2, j1 = j0 + 1;
                if (i0 - j0 > WINDOW) sf[nj][0] = NEG_INF;
                if (i0 - j1 > WINDOW) sf[nj][1] = NEG_INF;
                if (i1 - j0 > WINDOW) sf[nj][2] = NEG_INF;
                if (i1 - j1 > WINDOW) sf[nj][3] = NEG_INF;
            }
        }

        float mx0 = -1e30f, mx1 = -1e30f;
        #pragma unroll
        for (int nj = 0; nj < 8; nj++) {
            mx0 = fmaxf(mx0, fmaxf(sf[nj][0], sf[nj][1]));
            mx1 = fmaxf(mx1, fmaxf(sf[nj][2], sf[nj][3]));
        }
        mx0 = fmaxf(mx0, __shfl_xor_sync(0xffffffffu, mx0, 1));
        mx0 = fmaxf(mx0, __shfl_xor_sync(0xffffffffu, mx0, 2));
        mx1 = fmaxf(mx1, __shfl_xor_sync(0xffffffffu, mx1, 1));
        mx1 = fmaxf(mx1, __shfl_xor_sync(0xffffffffu, mx1, 2));
        const float mn0 = fmaxf(m0, mx0), mn1 = fmaxf(m1, mx1);
        float s0 = 0.f, s1 = 0.f;
        #pragma unroll
        for (int nj = 0; nj < 8; nj++) {
            sf[nj][0] = __expf(sf[nj][0] - mn0);
            sf[nj][1] = __expf(sf[nj][1] - mn0);
            sf[nj][2] = __expf(sf[nj][2] - mn1);
            sf[nj][3] = __expf(sf[nj][3] - mn1);
            s0 += sf[nj][0] + sf[nj][1];
            s1 += sf[nj][2] + sf[nj][3];
        }
        s0 += __shfl_xor_sync(0xffffffffu, s0, 1);
        s0 += __shfl_xor_sync(0xffffffffu, s0, 2);
        s1 += __shfl_xor_sync(0xffffffffu, s1, 1);
        s1 += __shfl_xor_sync(0xffffffffu, s1, 2);
        const float a0 = __expf(m0 - mn0), a1 = __expf(m1 - mn1);
        l0 = l0 * a0 + s0; l1 = l1 * a1 + s1;
        m0 = mn0; m1 = mn1;
        #pragma unroll
        for (int nj = 0; nj < 8; nj++) {
            O[nj][0] *= a0; O[nj][1] *= a0;
            O[nj][2] *= a1; O[nj][3] *= a1;
        }

        #pragma unroll
        for (int kt = 0; kt < 4; kt++) {
            uint32_t pah[4], pal[4];
            split2(sf[2 * kt][0],     sf[2 * kt][1],     pah[0], pal[0]);
            split2(sf[2 * kt][2],     sf[2 * kt][3],     pah[1], pal[1]);
            split2(sf[2 * kt + 1][0], sf[2 * kt + 1][1], pah[2], pal[2]);
            split2(sf[2 * kt + 1][2], sf[2 * kt + 1][3], pah[3], pal[3]);
            #pragma unroll
            for (int ng = 0; ng < 4; ng++) {
                uint32_t vh[4], vl[4];
                uint32_t a = kbase + ((kt * 16 + (lane & 15)) * AP
                                      + ng * 16 + 8 * (lane >> 4)) * 2;
                ldsm4t(vh[0], vh[1], vh[2], vh[3], a + ATT_VH * 2);
                ldsm4t(vl[0], vl[1], vl[2], vl[3], a + ATT_VL * 2);
                mma16816(O[2 * ng],     pah, &vh[0]);
                mma16816(O[2 * ng],     pah, &vl[0]);
                mma16816(O[2 * ng],     pal, &vh[0]);
                mma16816(O[2 * ng + 1], pah, &vh[2]);
                mma16816(O[2 * ng + 1], pah, &vl[2]);
                mma16816(O[2 * ng + 1], pal, &vh[2]);
            }
        }
    }

    const float inv0 = 1.f / l0, inv1 = 1.f / l1;
    const int r0g = qs + wq + (lane >> 2);
    const size_t base0 = ((size_t)(b * SEQ + r0g)) * EMBED + h * HDIM;
    #pragma unroll
    for (int nj = 0; nj < 8; nj++) {
        const int c = nj * 8 + (lane & 3) * 2;
        uint32_t hp, lp;
        split2h(O[nj][0] * inv0, O[nj][1] * inv0, hp, lp);
        *(uint32_t*)&ctxh[base0 + c] = hp;
        *(uint32_t*)&ctxl[base0 + c] = lp;
        split2h(O[nj][2] * inv1, O[nj][3] * inv1, hp, lp);
        *(uint32_t*)&ctxh[base0 + (size_t)8 * EMBED + c] = hp;
        *(uint32_t*)&ctxl[base0 + (size_t)8 * EMBED + c] = lp;
    }
}

// ---------------------------------------------------------------------------
// Launch
// ---------------------------------------------------------------------------
extern "C" void kernel_launch(void* const* d_in, const int* in_sizes, int n_in,
                              void* d_out, int out_size)
{
    const float* x     = (const float*)d_in[0];
    const float* w_qkv = (const float*)d_in[1];
    const float* b_qkv = (const float*)d_in[2];
    const float* w_out = (const float*)d_in[3];
    const float* b_out = (const float*)d_in[4];
    float* out = (float*)d_out;

    __nv_bfloat16 *qkvh, *qkvl;
    __half *xh, *xl, *wq16, *wo16, *ctxh, *ctxl;
    cudaGetSymbolAddress((void**)&qkvh, g_qkvh);
    cudaGetSymbolAddress((void**)&qkvl, g_qkvl);
    cudaGetSymbolAddress((void**)&xh,   g_xh);
    cudaGetSymbolAddress((void**)&xl,   g_xl);
    cudaGetSymbolAddress((void**)&wq16, g_wq16);
    cudaGetSymbolAddress((void**)&wo16, g_wo16);
    cudaGetSymbolAddress((void**)&ctxh, g_ctxh);
    cudaGetSymbolAddress((void**)&ctxl, g_ctxl);

    cudaFuncSetAttribute(hsgemm<true>,  cudaFuncAttributeMaxDynamicSharedMemorySize, GEMM_SMEM);
    cudaFuncSetAttribute(hsgemm<false>, cudaFuncAttributeMaxDynamicSharedMemorySize, GEMM_SMEM);
    cudaFuncSetAttribute(attn_tc, cudaFuncAttributeMaxDynamicSharedMemorySize, ATT_SMEM);

    // 0) x -> fp16 hi/lo; weights -> fp16
    {
        int n4 = MROWS * EMBED / 4;
        splith_kernel<<<(n4 + 255) / 256, 256>>>(x, xh, xl, n4);
        n4 = EMBED * QKV_N / 4;
        cvth_kernel<<<(n4 + 255) / 256, 256>>>(w_qkv, wq16, n4);
        n4 = EMBED * EMBED / 4;
        cvth_kernel<<<(n4 + 255) / 256, 256>>>(w_out, wo16, n4);
    }

    // 1) QKV projection (fp16 TC) -> bf16 hi/lo qkv
    {
        dim3 grid(QKV_N / BN, MROWS / BM);
        hsgemm<true><<<grid, 256, GEMM_SMEM>>>(MROWS, QKV_N, EMBED,
                                               xh, xl, wq16, b_qkv,
                                               nullptr, qkvh, qkvl);
    }
    // 2) Tensor-core attention -> fp16 hi/lo ctx
    {
        dim3 grid(SEQ / 64, HEADS, BATCH);
        attn_tc<<<grid, 128, ATT_SMEM>>>(qkvh, qkvl, ctxh, ctxl);
    }
    // 3) Output projection (fp16 TC) -> fp32 out
    {
        dim3 grid(EMBED / BN, MROWS / BM);
        hsgemm<false><<<grid, 256, GEMM_SMEM>>>(MROWS, EMBED, EMBED,
                                                ctxh, ctxl, wo16, b_out,
                                                out, nullptr, nullptr);
    }
}

// round 8
// speedup vs baseline: 3.5340x; 1.0617x over previous
#include <cuda_runtime.h>
#include <cuda_bf16.h>
#include <cuda_fp16.h>
#include <cstdint>

#define BATCH   4
#define SEQ     2048
#define EMBED   1024
#define HEADS   16
#define HDIM    64
#define NGLOBAL 4
#define WINDOW  256

#define MROWS   (BATCH * SEQ)          // 8192
#define QKV_N   (3 * EMBED)            // 3072

// ---------------------------------------------------------------------------
// Scratch (device globals: allocation-guard-safe)
// ---------------------------------------------------------------------------
__device__ __nv_bfloat16 g_qkvh[(size_t)MROWS * QKV_N];   // bf16 hi (attn input)
__device__ __nv_bfloat16 g_qkvl[(size_t)MROWS * QKV_N];   // bf16 lo
__device__ __half        g_xh  [(size_t)MROWS * EMBED];   // fp16 hi
__device__ __half        g_xl  [(size_t)MROWS * EMBED];   // fp16 lo
__device__ __half        g_wq16[(size_t)EMBED * QKV_N];   // fp16 weights
__device__ __half        g_wo16[(size_t)EMBED * EMBED];
__device__ __half        g_ctxh[(size_t)MROWS * EMBED];   // fp16 hi
__device__ __half        g_ctxl[(size_t)MROWS * EMBED];   // fp16 lo

// ---------------------------------------------------------------------------
// Helpers
// ---------------------------------------------------------------------------
__device__ __forceinline__ void cp16(uint32_t dst, const void* src) {
    asm volatile("cp.async.cg.shared.global [%0], [%1], 16;\n"
                 :: "r"(dst), "l"(src));
}
__device__ __forceinline__ void ldsm4(uint32_t& r0, uint32_t& r1,
                                      uint32_t& r2, uint32_t& r3, uint32_t a) {
    asm volatile("ldmatrix.sync.aligned.m8n8.x4.shared.b16 {%0,%1,%2,%3},[%4];\n"
                 : "=r"(r0), "=r"(r1), "=r"(r2), "=r"(r3) : "r"(a));
}
__device__ __forceinline__ void ldsm4t(uint32_t& r0, uint32_t& r1,
                                       uint32_t& r2, uint32_t& r3, uint32_t a) {
    asm volatile("ldmatrix.sync.aligned.m8n8.x4.trans.shared.b16 {%0,%1,%2,%3},[%4];\n"
                 : "=r"(r0), "=r"(r1), "=r"(r2), "=r"(r3) : "r"(a));
}
// bf16 mma (attention)
__device__ __forceinline__ void mma16816(float* c, const uint32_t* a,
                                         const uint32_t* b) {
    asm volatile(
        "mma.sync.aligned.m16n8k16.row.col.f32.bf16.bf16.f32 "
        "{%0,%1,%2,%3},{%4,%5,%6,%7},{%8,%9},{%0,%1,%2,%3};\n"
        : "+f"(c[0]), "+f"(c[1]), "+f"(c[2]), "+f"(c[3])
        : "r"(a[0]), "r"(a[1]), "r"(a[2]), "r"(a[3]), "r"(b[0]), "r"(b[1]));
}
// fp16 mma (projections)
__device__ __forceinline__ void mma16816h(float* c, const uint32_t* a,
                                          const uint32_t* b) {
    asm volatile(
        "mma.sync.aligned.m16n8k16.row.col.f32.f16.f16.f32 "
        "{%0,%1,%2,%3},{%4,%5,%6,%7},{%8,%9},{%0,%1,%2,%3};\n"
        : "+f"(c[0]), "+f"(c[1]), "+f"(c[2]), "+f"(c[3])
        : "r"(a[0]), "r"(a[1]), "r"(a[2]), "r"(a[3]), "r"(b[0]), "r"(b[1]));
}
// bf16 hi/lo packed split
__device__ __forceinline__ void split2(float a, float b,
                                       uint32_t& h, uint32_t& l) {
    __nv_bfloat16 ha = __float2bfloat16(a), hb = __float2bfloat16(b);
    __nv_bfloat16 la = __float2bfloat16(a - __bfloat162float(ha));
    __nv_bfloat16 lb = __float2bfloat16(b - __bfloat162float(hb));
    h = ((uint32_t)__bfloat16_as_ushort(hb) << 16) | __bfloat16_as_ushort(ha);
    l = ((uint32_t)__bfloat16_as_ushort(lb) << 16) | __bfloat16_as_ushort(la);
}
// fp16 hi/lo packed split
__device__ __forceinline__ void split2h(float a, float b,
                                        uint32_t& h, uint32_t& l) {
    __half ha = __float2half_rn(a), hb = __float2half_rn(b);
    __half la = __float2half_rn(a - __half2float(ha));
    __half lb = __float2half_rn(b - __half2float(hb));
    h = ((uint32_t)__half_as_ushort(hb) << 16) | __half_as_ushort(ha);
    l = ((uint32_t)__half_as_ushort(lb) << 16) | __half_as_ushort(la);
}

// ---------------------------------------------------------------------------
// Prep kernels
// ---------------------------------------------------------------------------
__global__ void splith_kernel(const float* __restrict__ src,
                              __half* __restrict__ hi,
                              __half* __restrict__ lo, int n4)
{
    int i = blockIdx.x * blockDim.x + threadIdx.x;
    if (i >= n4) return;
    float4 v = ((const float4*)src)[i];
    uint32_t h0, l0, h1, l1;
    split2h(v.x, v.y, h0, l0);
    split2h(v.z, v.w, h1, l1);
    ((uint2*)hi)[i] = make_uint2(h0, h1);
    ((uint2*)lo)[i] = make_uint2(l0, l1);
}

__global__ void cvth_kernel(const float* __restrict__ src,
                            __half* __restrict__ dst, int n4)
{
    int i = blockIdx.x * blockDim.x + threadIdx.x;
    if (i >= n4) return;
    float4 v = ((const float4*)src)[i];
    __half2 a = __floats2half2_rn(v.x, v.y);
    __half2 b = __floats2half2_rn(v.z, v.w);
    ((uint2*)dst)[i] = make_uint2(*(uint32_t*)&a, *(uint32_t*)&b);
}

// ---------------------------------------------------------------------------
// fp16 tensor-core GEMM, 2-term split: C = (Ah+Al) @ B + bias, fp32 accum.
// 128x128 CTA tile, BKK=64 K-stage, 2-stage double buffer, 8 warps as 4x2
// (32x64 warp tiles), 2 CTAs/SM.
// SPLIT=false: fp32 C.  SPLIT=true: bf16 hi/lo C.
// ---------------------------------------------------------------------------
#define BM 128
#define BN 128
#define BKK 64
#define ALD (BKK + 8)                      // 72 halves (144B row)
#define BLD (BN + 8)                       // 136 halves (272B row)
#define OFF_AH 0
#define OFF_AL (BM * ALD)                  // 9216
#define OFF_B  (2 * BM * ALD)              // 18432
#define STAGE_H (2 * BM * ALD + BKK * BLD) // 27136 halves
#define GEMM_SMEM (2 * STAGE_H * 2)        // 108544 bytes

template <bool SPLIT>
__global__ __launch_bounds__(256, 2) void hsgemm(
    int M, int N, int K,
    const __half* __restrict__ Ah, const __half* __restrict__ Al,
    const __half* __restrict__ B16,
    const float* __restrict__ bias, float* __restrict__ C,
    __nv_bfloat16* __restrict__ Ch, __nv_bfloat16* __restrict__ Cl)
{
    extern __shared__ __half sm[];
    const int tid = threadIdx.x;
    const int bm = blockIdx.y, bn = blockIdx.x;
    const int wid = tid >> 5, lane = tid & 31;
    const int wm = (wid >> 1) * 32, wn = (wid & 1) * 64;

    const uint32_t smem_base = (uint32_t)__cvta_generic_to_shared(sm);

    float acc[2][8][4];
    #pragma unroll
    for (int mi = 0; mi < 2; mi++)
        #pragma unroll
        for (int nj = 0; nj < 8; nj++)
            #pragma unroll
            for (int r = 0; r < 4; r++) acc[mi][nj][r] = 0.f;

    const int NK = K / BKK;

    auto load_stage = [&](int s, int kt) {
        const uint32_t base = smem_base + s * (STAGE_H * 2);
        const int k0 = kt * BKK;
        #pragma unroll
        for (int i = 0; i < 4; i++) {
            int idx = tid + i * 256;                  // 0..1023
            int r = idx >> 3, c = (idx & 7) << 3;     // A: 128 rows x 8 chunks
            size_t aoff = (size_t)(bm * BM + r) * K + k0 + c;
            cp16(base + (OFF_AH + r * ALD + c) * 2, Ah + aoff);
            cp16(base + (OFF_AL + r * ALD + c) * 2, Al + aoff);
            int rb = idx >> 4, cb = (idx & 15) << 3;  // B: 64 rows x 16 chunks
            size_t boff = (size_t)(k0 + rb) * N + bn * BN + cb;
            cp16(base + (OFF_B + rb * BLD + cb) * 2, B16 + boff);
        }
        asm volatile("cp.async.commit_group;\n");
    };

    load_stage(0, 0);

    for (int kt = 0; kt < NK; kt++) {
        if (kt + 1 < NK) {
            load_stage((kt + 1) & 1, kt + 1);        // buffer freed by prior trailing sync
            asm volatile("cp.async.wait_group 1;\n");
        } else {
            asm volatile("cp.async.wait_group 0;\n");
        }
        __syncthreads();

        const uint32_t base = smem_base + (kt & 1) * (STAGE_H * 2);

        #pragma unroll
        for (int ks = 0; ks < 4; ks++) {
            const int k = ks * 16;
            uint32_t ah[2][4], al[2][4];
            #pragma unroll
            for (int mi = 0; mi < 2; mi++) {
                int row = wm + mi * 16 + (lane & 15);
                int col = k + (lane >> 4) * 8;
                ldsm4(ah[mi][0], ah[mi][1], ah[mi][2], ah[mi][3],
                      base + (OFF_AH + row * ALD + col) * 2);
                ldsm4(al[mi][0], al[mi][1], al[mi][2], al[mi][3],
                      base + (OFF_AL + row * ALD + col) * 2);
            }
            uint32_t bf[4][4];
            #pragma unroll
            for (int ng = 0; ng < 4; ng++) {
                int row = k + (lane & 15);
                int col = wn + ng * 16 + (lane >> 4) * 8;
                ldsm4t(bf[ng][0], bf[ng][1], bf[ng][2], bf[ng][3],
                       base + (OFF_B + row * BLD + col) * 2);
            }
            #pragma unroll
            for (int mi = 0; mi < 2; mi++) {
                #pragma unroll
                for (int nj = 0; nj < 8; nj++) {
                    const uint32_t* bp = &bf[nj >> 1][(nj & 1) * 2];
                    mma16816h(acc[mi][nj], ah[mi], bp);
                    mma16816h(acc[mi][nj], al[mi], bp);
                }
            }
        }
        __syncthreads();
    }

    #pragma unroll
    for (int mi = 0; mi < 2; mi++) {
        #pragma unroll
        for (int nj = 0; nj < 8; nj++) {
            int r0 = bm * BM + wm + mi * 16 + (lane >> 2);
            int c0 = bn * BN + wn + nj * 8 + (lane & 3) * 2;
            float b0 = bias[c0], b1 = bias[c0 + 1];
            float v00 = acc[mi][nj][0] + b0, v01 = acc[mi][nj][1] + b1;
            float v10 = acc[mi][nj][2] + b0, v11 = acc[mi][nj][3] + b1;
            if (SPLIT) {
                uint32_t hp, lp;
                split2(v00, v01, hp, lp);
                *(uint32_t*)&Ch[(size_t)r0 * N + c0] = hp;
                *(uint32_t*)&Cl[(size_t)r0 * N + c0] = lp;
                split2(v10, v11, hp, lp);
                *(uint32_t*)&Ch[(size_t)(r0 + 8) * N + c0] = hp;
                *(uint32_t*)&Cl[(size_t)(r0 + 8) * N + c0] = lp;
            } else {
                *(float2*)&C[(size_t)r0 * N + c0]       = make_float2(v00, v01);
                *(float2*)&C[(size_t)(r0 + 8) * N + c0] = make_float2(v10, v11);
            }
        }
    }
}

// ---------------------------------------------------------------------------
// Tensor-core flash attention (bf16 3-term; ctx epilogue -> fp16 hi/lo).
// ---------------------------------------------------------------------------
#define AP 72
#define ATT_SQH 0
#define ATT_SQL (64 * AP)
#define ATT_STAGE0 (2 * 64 * AP)
#define ATT_STAGE_SZ (4 * 64 * AP)
#define ATT_KH 0
#define ATT_KL (64 * AP)
#define ATT_VH (2 * 64 * AP)
#define ATT_VL (3 * 64 * AP)
#define ATT_SMEM ((2 * 64 * AP + 2 * 4 * 64 * AP) * 2)

__global__ __launch_bounds__(128) void attn_tc(
    const __nv_bfloat16* __restrict__ qh_g,
    const __nv_bfloat16* __restrict__ ql_g,
    __half* __restrict__ ctxh,
    __half* __restrict__ ctxl)
{
    extern __shared__ __nv_bfloat16 smb[];
    const uint32_t sb = (uint32_t)__cvta_generic_to_shared(smb);
    const int qb = blockIdx.x, h = blockIdx.y, b = blockIdx.z;
    const int qs = qb * 64;
    const bool isg = (h < NGLOBAL);
    const int tid = threadIdx.x, lane = tid & 31, warp = tid >> 5;
    const int wq = warp * 16;
    const size_t rowbase = (size_t)(b * SEQ) * QKV_N;
    const float NEG_INF = __int_as_float(0xff800000u);

    #pragma unroll
    for (int i = 0; i < 4; i++) {
        int idx = tid + i * 128;
        int r = idx >> 3, c8 = (idx & 7) * 8;
        size_t src = rowbase + (size_t)(qs + r) * QKV_N + h * HDIM + c8;
        cp16(sb + (ATT_SQH + r * AP + c8) * 2, qh_g + src);
        cp16(sb + (ATT_SQL + r * AP + c8) * 2, ql_g + src);
    }
    asm volatile("cp.async.commit_group;\n");

    const int kb0 = isg ? 0 : max(0, qb - 4);

    auto load_kv = [&](int kb, int s) {
        const uint32_t base = sb + (ATT_STAGE0 + s * ATT_STAGE_SZ) * 2;
        const int ks = kb * 64;
        #pragma unroll
        for (int i = 0; i < 4; i++) {
            int idx = tid + i * 128;
            int r = idx >> 3, c8 = (idx & 7) * 8;
            size_t src = rowbase + (size_t)(ks + r) * QKV_N + EMBED + h * HDIM + c8;
            cp16(base + (ATT_KH + r * AP + c8) * 2, qh_g + src);
            cp16(base + (ATT_KL + r * AP + c8) * 2, ql_g + src);
            cp16(base + (ATT_VH + r * AP + c8) * 2, qh_g + src + EMBED);
            cp16(base + (ATT_VL + r * AP + c8) * 2, ql_g + src + EMBED);
        }
        asm volatile("cp.async.commit_group;\n");
    };

    load_kv(kb0, 0);

    float m0 = -1e30f, m1 = -1e30f, l0 = 0.f, l1 = 0.f;
    float O[8][4];
    #pragma unroll
    for (int nj = 0; nj < 8; nj++)
        #pragma unroll
        for (int r = 0; r < 4; r++) O[nj][r] = 0.f;

    uint32_t qfh[4][4], qfl[4][4];
    bool qloaded = false;

    for (int kb = kb0; kb <= qb; kb++) {
        const int s = (kb - kb0) & 1;
        const int ks = kb * 64;
        __syncthreads();
        if (kb < qb) {
            load_kv(kb + 1, s ^ 1);
            asm volatile("cp.async.wait_group 1;\n");
        } else {
            asm volatile("cp.async.wait_group 0;\n");
        }
        __syncthreads();

        if (!qloaded) {
            qloaded = true;
            #pragma unroll
            for (int kt = 0; kt < 4; kt++) {
                uint32_t a = sb + (ATT_SQH + (wq + (lane & 15)) * AP
                                   + kt * 16 + 8 * (lane >> 4)) * 2;
                ldsm4(qfh[kt][0], qfh[kt][1], qfh[kt][2], qfh[kt][3], a);
                ldsm4(qfl[kt][0], qfl[kt][1], qfl[kt][2], qfl[kt][3],
                      a + (ATT_SQL - ATT_SQH) * 2);
            }
        }

        const uint32_t kbase = sb + (ATT_STAGE0 + s * ATT_STAGE_SZ) * 2;

        float sf[8][4];
        #pragma unroll
        for (int nj = 0; nj < 8; nj++)
            #pragma unroll
            for (int r = 0; r < 4; r++) sf[nj][r] = 0.f;

        #pragma unroll
        for (int kt = 0; kt < 4; kt++) {
            #pragma unroll
            for (int ng = 0; ng < 4; ng++) {
                uint32_t kh[4], kl[4];
                uint32_t a = kbase + ((ng * 16 + (lane & 15)) * AP
                                      + kt * 16 + 8 * (lane >> 4)) * 2;
                ldsm4(kh[0], kh[1], kh[2], kh[3], a + ATT_KH * 2);
                ldsm4(kl[0], kl[1], kl[2], kl[3], a + ATT_KL * 2);
                uint32_t bh0[2] = {kh[0], kh[2]}, bh1[2] = {kh[1], kh[3]};
                uint32_t bl0[2] = {kl[0], kl[2]}, bl1[2] = {kl[1], kl[3]};
                mma16816(sf[2 * ng],     qfh[kt], bh0);
                mma16816(sf[2 * ng],     qfh[kt], bl0);
                mma16816(sf[2 * ng],     qfl[kt], bh0);
                mma16816(sf[2 * ng + 1], qfh[kt], bh1);
                mma16816(sf[2 * ng + 1], qfh[kt], bl1);
                mma16816(sf[2 * ng + 1], qfl[kt], bh1);
            }
        }
        #pragma unroll
        for (int nj = 0; nj < 8; nj++)
            #pragma unroll
            for (int r = 0; r < 4; r++) sf[nj][r] *= 0.125f;

        const int i0 = qs + wq + (lane >> 2);
        const int i1 = i0 + 8;
        const int mode = (kb == qb) ? 1 : ((!isg && (qb - kb) == 4) ? 2 : 0);
        if (mode == 1) {
            #pragma unroll
            for (int nj = 0; nj < 8; nj++) {
                int j0 = ks + nj * 8 + (lane & 3) * 2, j1 = j0 + 1;
                if (j0 > i0) sf[nj][0] = NEG_INF;
                if (j1 > i0) sf[nj][1] = NEG_INF;
                if (j0 > i1) sf[nj][2] = NEG_INF;
                if (j1 > i1) sf[nj][3] = NEG_INF;
            }
        } else if (mode == 2) {
            #pragma unroll
            for (int nj = 0; nj < 8; nj++) {
                int j0 = ks + nj * 8 + (lane & 3) * 2, j1 = j0 + 1;
                if (i0 - j0 > WINDOW) sf[nj][0] = NEG_INF;
                if (i0 - j1 > WINDOW) sf[nj][1] = NEG_INF;
                if (i1 - j0 > WINDOW) sf[nj][2] = NEG_INF;
                if (i1 - j1 > WINDOW) sf[nj][3] = NEG_INF;
            }
        }

        float mx0 = -1e30f, mx1 = -1e30f;
        #pragma unroll
        for (int nj = 0; nj < 8; nj++) {
            mx0 = fmaxf(mx0, fmaxf(sf[nj][0], sf[nj][1]));
            mx1 = fmaxf(mx1, fmaxf(sf[nj][2], sf[nj][3]));
        }
        mx0 = fmaxf(mx0, __shfl_xor_sync(0xffffffffu, mx0, 1));
        mx0 = fmaxf(mx0, __shfl_xor_sync(0xffffffffu, mx0, 2));
        mx1 = fmaxf(mx1, __shfl_xor_sync(0xffffffffu, mx1, 1));
        mx1 = fmaxf(mx1, __shfl_xor_sync(0xffffffffu, mx1, 2));
        const float mn0 = fmaxf(m0, mx0), mn1 = fmaxf(m1, mx1);
        float s0 = 0.f, s1 = 0.f;
        #pragma unroll
        for (int nj = 0; nj < 8; nj++) {
            sf[nj][0] = __expf(sf[nj][0] - mn0);
            sf[nj][1] = __expf(sf[nj][1] - mn0);
            sf[nj][2] = __expf(sf[nj][2] - mn1);
            sf[nj][3] = __expf(sf[nj][3] - mn1);
            s0 += sf[nj][0] + sf[nj][1];
            s1 += sf[nj][2] + sf[nj][3];
        }
        s0 += __shfl_xor_sync(0xffffffffu, s0, 1);
        s0 += __shfl_xor_sync(0xffffffffu, s0, 2);
        s1 += __shfl_xor_sync(0xffffffffu, s1, 1);
        s1 += __shfl_xor_sync(0xffffffffu, s1, 2);
        const float a0 = __expf(m0 - mn0), a1 = __expf(m1 - mn1);
        l0 = l0 * a0 + s0; l1 = l1 * a1 + s1;
        m0 = mn0; m1 = mn1;
        #pragma unroll
        for (int nj = 0; nj < 8; nj++) {
            O[nj][0] *= a0; O[nj][1] *= a0;
            O[nj][2] *= a1; O[nj][3] *= a1;
        }

        #pragma unroll
        for (int kt = 0; kt < 4; kt++) {
            uint32_t pah[4], pal[4];
            split2(sf[2 * kt][0],     sf[2 * kt][1],     pah[0], pal[0]);
            split2(sf[2 * kt][2],     sf[2 * kt][3],     pah[1], pal[1]);
            split2(sf[2 * kt + 1][0], sf[2 * kt + 1][1], pah[2], pal[2]);
            split2(sf[2 * kt + 1][2], sf[2 * kt + 1][3], pah[3], pal[3]);
            #pragma unroll
            for (int ng = 0; ng < 4; ng++) {
                uint32_t vh[4], vl[4];
                uint32_t a = kbase + ((kt * 16 + (lane & 15)) * AP
                                      + ng * 16 + 8 * (lane >> 4)) * 2;
                ldsm4t(vh[0], vh[1], vh[2], vh[3], a + ATT_VH * 2);
                ldsm4t(vl[0], vl[1], vl[2], vl[3], a + ATT_VL * 2);
                mma16816(O[2 * ng],     pah, &vh[0]);
                mma16816(O[2 * ng],     pah, &vl[0]);
                mma16816(O[2 * ng],     pal, &vh[0]);
                mma16816(O[2 * ng + 1], pah, &vh[2]);
                mma16816(O[2 * ng + 1], pah, &vl[2]);
                mma16816(O[2 * ng + 1], pal, &vh[2]);
            }
        }
    }

    const float inv0 = 1.f / l0, inv1 = 1.f / l1;
    const int r0g = qs + wq + (lane >> 2);
    const size_t base0 = ((size_t)(b * SEQ + r0g)) * EMBED + h * HDIM;
    #pragma unroll
    for (int nj = 0; nj < 8; nj++) {
        const int c = nj * 8 + (lane & 3) * 2;
        uint32_t hp, lp;
        split2h(O[nj][0] * inv0, O[nj][1] * inv0, hp, lp);
        *(uint32_t*)&ctxh[base0 + c] = hp;
        *(uint32_t*)&ctxl[base0 + c] = lp;
        split2h(O[nj][2] * inv1, O[nj][3] * inv1, hp, lp);
        *(uint32_t*)&ctxh[base0 + (size_t)8 * EMBED + c] = hp;
        *(uint32_t*)&ctxl[base0 + (size_t)8 * EMBED + c] = lp;
    }
}

// ---------------------------------------------------------------------------
// Launch
// ---------------------------------------------------------------------------
extern "C" void kernel_launch(void* const* d_in, const int* in_sizes, int n_in,
                              void* d_out, int out_size)
{
    const float* x     = (const float*)d_in[0];
    const float* w_qkv = (const float*)d_in[1];
    const float* b_qkv = (const float*)d_in[2];
    const float* w_out = (const float*)d_in[3];
    const float* b_out = (const float*)d_in[4];
    float* out = (float*)d_out;

    __nv_bfloat16 *qkvh, *qkvl;
    __half *xh, *xl, *wq16, *wo16, *ctxh, *ctxl;
    cudaGetSymbolAddress((void**)&qkvh, g_qkvh);
    cudaGetSymbolAddress((void**)&qkvl, g_qkvl);
    cudaGetSymbolAddress((void**)&xh,   g_xh);
    cudaGetSymbolAddress((void**)&xl,   g_xl);
    cudaGetSymbolAddress((void**)&wq16, g_wq16);
    cudaGetSymbolAddress((void**)&wo16, g_wo16);
    cudaGetSymbolAddress((void**)&ctxh, g_ctxh);
    cudaGetSymbolAddress((void**)&ctxl, g_ctxl);

    cudaFuncSetAttribute(hsgemm<true>,  cudaFuncAttributeMaxDynamicSharedMemorySize, GEMM_SMEM);
    cudaFuncSetAttribute(hsgemm<false>, cudaFuncAttributeMaxDynamicSharedMemorySize, GEMM_SMEM);
    cudaFuncSetAttribute(attn_tc, cudaFuncAttributeMaxDynamicSharedMemorySize, ATT_SMEM);

    // 0) x -> fp16 hi/lo; weights -> fp16
    {
        int n4 = MROWS * EMBED / 4;
        splith_kernel<<<(n4 + 255) / 256, 256>>>(x, xh, xl, n4);
        n4 = EMBED * QKV_N / 4;
        cvth_kernel<<<(n4 + 255) / 256, 256>>>(w_qkv, wq16, n4);
        n4 = EMBED * EMBED / 4;
        cvth_kernel<<<(n4 + 255) / 256, 256>>>(w_out, wo16, n4);
    }

    // 1) QKV projection (fp16 TC) -> bf16 hi/lo qkv
    {
        dim3 grid(QKV_N / BN, MROWS / BM);
        hsgemm<true><<<grid, 256, GEMM_SMEM>>>(MROWS, QKV_N, EMBED,
                                               xh, xl, wq16, b_qkv,
                                               nullptr, qkvh, qkvl);
    }
    // 2) Tensor-core attention -> fp16 hi/lo ctx
    {
        dim3 grid(SEQ / 64, HEADS, BATCH);
        attn_tc<<<grid, 128, ATT_SMEM>>>(qkvh, qkvl, ctxh, ctxl);
    }
    // 3) Output projection (fp16 TC) -> fp32 out
    {
        dim3 grid(EMBED / BN, MROWS / BM);
        hsgemm<false><<<grid, 256, GEMM_SMEM>>>(MROWS, EMBED, EMBED,
                                                ctxh, ctxl, wo16, b_out,
                                                out, nullptr, nullptr);
    }
}